// round 11
// baseline (speedup 1.0000x reference)
#include <cuda_runtime.h>
#include <math.h>
#include <stdint.h>

#define BDIM 1024
#define NB 4
#define NSEQ 1024
#define NHEADS 16
#define HDIM 64
#define ROWS (NB*NSEQ)   // 4096
#define MAXSEQ 1024

// ---------------- scratch (device globals; no allocation allowed) ----------------
__device__ float g_xn[(size_t)ROWS*BDIM];               // 16 MB
__device__ float g_qkv[(size_t)ROWS*3*BDIM];            // 48 MB
__device__ float g_ctx[(size_t)ROWS*BDIM];              // 16 MB
__device__ float g_y[(size_t)ROWS*BDIM];                // 16 MB
__device__ float g_mlp[(size_t)ROWS*4*BDIM];            // 64 MB
// tf32-rounded TRANSPOSED weights [N, K] K-major
__device__ float g_qkvw[(size_t)BDIM*3*BDIM];           // 12 MB
__device__ float g_projw[(size_t)BDIM*BDIM];            // 4 MB
__device__ float g_w1[(size_t)BDIM*4*BDIM];             // 16 MB
__device__ float g_w2[(size_t)4*BDIM*BDIM];             // 16 MB

// ---------------- helpers ----------------
__device__ __forceinline__ uint32_t f2tf(float x) {
    uint32_t r;
    asm("cvt.rna.tf32.f32 %0, %1;" : "=r"(r) : "f"(x));
    return r;
}
__device__ __forceinline__ float f2tff(float x) { return __uint_as_float(f2tf(x)); }

__device__ __forceinline__ void mma_tf32(float c[4], const uint32_t a[4], const uint32_t b[2]) {
    asm volatile(
        "mma.sync.aligned.m16n8k8.row.col.f32.tf32.tf32.f32 "
        "{%0,%1,%2,%3}, {%4,%5,%6,%7}, {%8,%9}, {%0,%1,%2,%3};"
        : "+f"(c[0]), "+f"(c[1]), "+f"(c[2]), "+f"(c[3])
        : "r"(a[0]), "r"(a[1]), "r"(a[2]), "r"(a[3]), "r"(b[0]), "r"(b[1]));
}

__device__ __forceinline__ void cp_async16(uint32_t smem_addr, const void* gptr) {
    asm volatile("cp.async.cg.shared.global [%0], [%1], 16;"
                 :: "r"(smem_addr), "l"(gptr));
}
__device__ __forceinline__ void cp_commit() { asm volatile("cp.async.commit_group;"); }
template<int N>
__device__ __forceinline__ void cp_wait() { asm volatile("cp.async.wait_group %0;" :: "n"(N)); }

// ---------------- weight transpose + tf32 round: out[n*K+k] = tf32(in[k*N+n]) ----------------
__global__ __launch_bounds__(256) void transpose_tf32_kernel(
    const float* __restrict__ in, float* __restrict__ out, int K, int N)
{
    __shared__ float t[32][33];
    const int n0 = blockIdx.x * 32, k0 = blockIdx.y * 32;
    const int tx = threadIdx.x & 31, ty = threadIdx.x >> 5;  // 32 x 8
    #pragma unroll
    for (int i = 0; i < 32; i += 8)
        t[ty + i][tx] = in[(size_t)(k0 + ty + i) * N + n0 + tx];
    __syncthreads();
    #pragma unroll
    for (int i = 0; i < 32; i += 8)
        out[(size_t)(n0 + ty + i) * K + k0 + tx] = f2tff(t[tx][ty + i]);
}

// ---------------- LayerNorm: warp per row (no smem, no barriers) ----------------
__global__ __launch_bounds__(256) void ln_kernel(const float* __restrict__ x,
    const float* __restrict__ g, const float* __restrict__ b, float* __restrict__ out)
{
    const int row  = blockIdx.x * 8 + (threadIdx.x >> 5);
    const int lane = threadIdx.x & 31;
    const float4* xr = reinterpret_cast<const float4*>(x + (size_t)row * BDIM);
    float4 v[8];
    float s = 0.0f;
    #pragma unroll
    for (int i = 0; i < 8; i++) {
        v[i] = xr[lane + 32 * i];
        s += v[i].x + v[i].y + v[i].z + v[i].w;
    }
    #pragma unroll
    for (int o = 16; o > 0; o >>= 1) s += __shfl_xor_sync(0xffffffffu, s, o);
    const float mu = s * (1.0f / BDIM);
    float q = 0.0f;
    #pragma unroll
    for (int i = 0; i < 8; i++) {
        v[i].x -= mu; v[i].y -= mu; v[i].z -= mu; v[i].w -= mu;
        q += v[i].x*v[i].x + v[i].y*v[i].y + v[i].z*v[i].z + v[i].w*v[i].w;
    }
    #pragma unroll
    for (int o = 16; o > 0; o >>= 1) q += __shfl_xor_sync(0xffffffffu, q, o);
    const float rinv = rsqrtf(q * (1.0f / BDIM) + 1e-5f);
    float4* orow = reinterpret_cast<float4*>(out + (size_t)row * BDIM);
    #pragma unroll
    for (int i = 0; i < 8; i++) {
        float4 gg = reinterpret_cast<const float4*>(g)[lane + 32 * i];
        float4 bb = reinterpret_cast<const float4*>(b)[lane + 32 * i];
        float4 o4;
        o4.x = f2tff(v[i].x * rinv * gg.x + bb.x);
        o4.y = f2tff(v[i].y * rinv * gg.y + bb.y);
        o4.z = f2tff(v[i].z * rinv * gg.z + bb.z);
        o4.w = f2tff(v[i].w * rinv * gg.w + bb.w);
        orow[lane + 32 * i] = o4;
    }
}

// ---------------- 2-stage cp.async TF32 GEMM v3: 256 threads, warp 64x32 ----------------
// Both operands [row][K] K-major stride 40; all fragment loads are LDS.64
// (k-slot bijection: lane t4 -> logical k {2t4, 2t4+1}). 16 HMMA : 12 LDS.64 per ks.
// 2 CTAs/SM -> 16 warps/SM latency hiding.
enum { EPI_BIAS = 0, EPI_GELU = 1, EPI_RESGATE = 2 };

#define G_ST 40                       // row stride words: per-16-lane-phase conflict-free
#define G_OPW (128*G_ST)              // 5120 words per operand per stage
#define GEMM_SMEM (2*2*G_OPW*4)       // 81920 bytes (2 stages x (A+B))

template<int EPI>
__global__ __launch_bounds__(256, 2) void tf32gemm_kernel(
    const float* __restrict__ A, const float* __restrict__ Wt,
    const float* __restrict__ bias, const float* __restrict__ res,
    const float* __restrict__ gate, float* __restrict__ C,
    int M, int N, int K)
{
    constexpr int BK = 32;
    extern __shared__ uint32_t sm[];
    const uint32_t sm_u = (uint32_t)__cvta_generic_to_shared(sm);

    const int tid  = threadIdx.x;
    const int lane = tid & 31;
    const int wid  = tid >> 5;
    const int g    = lane >> 2;
    const int t4   = lane & 3;
    const int mWarp = (wid >> 2) * 64;    // 0 or 64
    const int nWarp = (wid & 3) * 32;     // 0,32,64,96

    // global->smem mapping: 32 rows x 8 chunks per pass, 4 passes per operand
    const int lr = tid >> 3;           // 0..31
    const int lc = (tid & 7) * 4;      // word col 0..28

    const float* Ap = A  + (size_t)(blockIdx.y * 128 + lr) * K + lc;
    const float* Bp = Wt + (size_t)(blockIdx.x * 128 + lr) * K + lc;
    const uint32_t aDst = sm_u + (uint32_t)(lr * G_ST + lc) * 4;
    const uint32_t bDst = aDst + G_OPW * 4;

    const int nT = K / BK;

    // prologue: tile 0 -> stage 0
    #pragma unroll
    for (int p = 0; p < 4; p++) {
        cp_async16(aDst + (uint32_t)(p * 32 * G_ST) * 4, Ap + (size_t)(p * 32) * K);
        cp_async16(bDst + (uint32_t)(p * 32 * G_ST) * 4, Bp + (size_t)(p * 32) * K);
    }
    cp_commit();

    float acc[4][4][4] = {};

    for (int t = 0; t < nT; t++) {
        cp_wait<0>();
        __syncthreads();

        if (t + 1 < nT) {
            const uint32_t so = (uint32_t)(((t + 1) & 1) * 2 * G_OPW) * 4;
            const float* ap = Ap + (size_t)(t + 1) * BK;
            const float* bp = Bp + (size_t)(t + 1) * BK;
            #pragma unroll
            for (int p = 0; p < 4; p++) {
                cp_async16(aDst + so + (uint32_t)(p * 32 * G_ST) * 4, ap + (size_t)(p * 32) * K);
                cp_async16(bDst + so + (uint32_t)(p * 32 * G_ST) * 4, bp + (size_t)(p * 32) * K);
            }
            cp_commit();
        }

        const uint32_t* As = sm + (t & 1) * 2 * G_OPW;
        const uint32_t* Bs = As + G_OPW;
        #pragma unroll
        for (int ks = 0; ks < 4; ks++) {
            const int kA = ks * 8 + 2 * t4;    // k-slot bijection
            uint32_t bf[4][2];
            #pragma unroll
            for (int ni = 0; ni < 4; ni++) {
                uint2 bb = *reinterpret_cast<const uint2*>(&Bs[(nWarp + ni * 8 + g) * G_ST + kA]);
                bf[ni][0] = bb.x; bf[ni][1] = bb.y;
            }
            #pragma unroll
            for (int mi = 0; mi < 4; mi++) {
                const int mb = mWarp + mi * 16;
                uint2 a0 = *reinterpret_cast<const uint2*>(&As[(mb + g) * G_ST + kA]);
                uint2 a1 = *reinterpret_cast<const uint2*>(&As[(mb + g + 8) * G_ST + kA]);
                uint32_t af[4] = { a0.x, a1.x, a0.y, a1.y };
                #pragma unroll
                for (int ni = 0; ni < 4; ni++)
                    mma_tf32(acc[mi][ni], af, bf[ni]);
            }
        }
        // slot reuse ordered by next iteration's top-of-loop barrier
    }

    // epilogue
    const float gt = (EPI == EPI_RESGATE) ? gate[0] : 0.0f;
    #pragma unroll
    for (int mi = 0; mi < 4; mi++) {
        const int row0 = blockIdx.y * 128 + mWarp + mi * 16 + g;
        #pragma unroll
        for (int ni = 0; ni < 4; ni++) {
            const int col = blockIdx.x * 128 + nWarp + ni * 8 + t4 * 2;
            const float b0 = bias[col], b1 = bias[col + 1];
            #pragma unroll
            for (int h = 0; h < 2; h++) {
                const int row = row0 + h * 8;
                float v0 = acc[mi][ni][2 * h + 0] + b0;
                float v1 = acc[mi][ni][2 * h + 1] + b1;
                if (EPI == EPI_BIAS) {
                    v0 = f2tff(v0);
                    v1 = f2tff(v1);
                }
                if (EPI == EPI_GELU) {
                    v0 = f2tff(0.5f * v0 * (1.0f + erff(v0 * 0.70710678118654752f)));
                    v1 = f2tff(0.5f * v1 * (1.0f + erff(v1 * 0.70710678118654752f)));
                }
                if (EPI == EPI_RESGATE) {
                    const size_t off = (size_t)row * N + col;
                    v0 = res[off] + gt * v0;
                    v1 = res[off + 1] + gt * v1;
                }
                *reinterpret_cast<float2*>(C + (size_t)row * N + col) = make_float2(v0, v1);
            }
        }
    }
}

// ---------------- Fused flash attention (TF32; O^T form; cp.async K/V pipeline) ----------------
#define KST 72
#define VST 76
#define FL_SLOTW (64*KST + 64*VST)               // 9472 words per KV slot
#define FL_MK    (2*FL_SLOTW)                    // mki[2][64]
#define FL_REL   (FL_MK + 128)                   // rel_s[2047]
#define FL_WORDS (FL_REL + 2048)
#define FL_SMEM  (FL_WORDS*4)                    // 84480 bytes

__global__ __launch_bounds__(256, 2) void flash_attn_kernel(
    const float* __restrict__ qkv, const int* __restrict__ mask,
    const float* __restrict__ rel, float* __restrict__ ctx)
{
    constexpr float SCALE = 0.125f;
    constexpr float L2E = 1.4426950408889634f;

    extern __shared__ __align__(16) uint32_t sm[];
    const uint32_t sm_u = (uint32_t)__cvta_generic_to_shared(sm);
    const int* mki  = reinterpret_cast<const int*>(sm + FL_MK);
    float* rel_s    = reinterpret_cast<float*>(sm + FL_REL);
    uint32_t* Qst   = sm + FL_SLOTW;   // overlays KV slot 1

    const int bh = blockIdx.y;
    const int b = bh >> 4, h = bh & 15;
    const int i0 = blockIdx.x * 128;
    const int tid = threadIdx.x, lane = tid & 31, w = tid >> 5;
    const int g = lane >> 2, t4 = lane & 3;

    const int ldr = tid >> 2;
    const int ldc = (tid & 3) * 16;
    const float* kvbase = qkv + (size_t)(b * NSEQ + ldr) * (3 * BDIM) + BDIM + h * HDIM + ldc;

    // prologue: prefetch tile 0 -> slot 0
    {
        const float* kp = kvbase;
        const uint32_t kdst = sm_u + (uint32_t)(ldr * KST + ldc) * 4;
        const uint32_t vdst = sm_u + (uint32_t)(64 * KST + ldr * VST + ldc) * 4;
        #pragma unroll
        for (int i = 0; i < 4; i++) {
            cp_async16(kdst + 16 * i, kp + 4 * i);
            cp_async16(vdst + 16 * i, kp + BDIM + 4 * i);
        }
        if (tid < 16)
            cp_async16(sm_u + (uint32_t)(FL_MK + tid * 4) * 4, mask + b * NSEQ + tid * 4);
        cp_commit();
    }

    for (int idx = tid; idx < 2 * MAXSEQ - 1; idx += 256)
        rel_s[idx] = rel[(size_t)idx * NHEADS + h];

    {
        const int r = tid >> 1;
        const int c0 = (tid & 1) * 32;
        const float* qp = qkv + ((size_t)(b * NSEQ + i0 + r)) * (3 * BDIM) + h * HDIM + c0;
        #pragma unroll
        for (int i = 0; i < 8; i++)
            *reinterpret_cast<uint4*>(&Qst[r * KST + c0 + 4 * i]) =
                *reinterpret_cast<const uint4*>(qp + 4 * i);
    }
    __syncthreads();

    uint32_t Qa[8][4];
    #pragma unroll
    for (int kt = 0; kt < 8; kt++) {
        uint2 q0 = *reinterpret_cast<const uint2*>(&Qst[(w * 16 + g) * KST + kt * 8 + 2 * t4]);
        uint2 q1 = *reinterpret_cast<const uint2*>(&Qst[(w * 16 + g + 8) * KST + kt * 8 + 2 * t4]);
        Qa[kt][0] = q0.x; Qa[kt][1] = q1.x; Qa[kt][2] = q0.y; Qa[kt][3] = q1.y;
    }

    const int irow0 = i0 + w * 16 + g;
    const int irow1 = irow0 + 8;
    const int mi0 = mask[b * NSEQ + irow0];
    const int mi1 = mask[b * NSEQ + irow1];

    float m0 = -INFINITY, m1 = -INFINITY, l0 = 0.0f, l1 = 0.0f;
    float OcT[4][2][4] = {};

    for (int jt = 0; jt < NSEQ / 64; jt++) {
        cp_wait<0>();
        __syncthreads();

        if (jt + 1 < NSEQ / 64) {
            const int ns = (jt + 1) & 1;
            const float* kp = kvbase + (size_t)(jt + 1) * 64 * (3 * BDIM);
            const uint32_t kdst = sm_u + (uint32_t)(ns * FL_SLOTW + ldr * KST + ldc) * 4;
            const uint32_t vdst = sm_u + (uint32_t)(ns * FL_SLOTW + 64 * KST + ldr * VST + ldc) * 4;
            #pragma unroll
            for (int i = 0; i < 4; i++) {
                cp_async16(kdst + 16 * i, kp + 4 * i);
                cp_async16(vdst + 16 * i, kp + BDIM + 4 * i);
            }
            if (tid < 16)
                cp_async16(sm_u + (uint32_t)(FL_MK + ns * 64 + tid * 4) * 4,
                           mask + b * NSEQ + (jt + 1) * 64 + tid * 4);
            cp_commit();
        }

        const int slot = jt & 1;
        const uint32_t* Ks = sm + slot * FL_SLOTW;
        const uint32_t* Vs = sm + slot * FL_SLOTW + 64 * KST;
        const int* mkp = mki + slot * 64;

        float S[8][4] = {};
        #pragma unroll
        for (int nt = 0; nt < 8; nt++) {
            #pragma unroll
            for (int kt = 0; kt < 8; kt++) {
                uint2 kk = *reinterpret_cast<const uint2*>(&Ks[(nt * 8 + g) * KST + kt * 8 + 2 * t4]);
                uint32_t bf[2] = { kk.x, kk.y };
                mma_tf32(S[nt], Qa[kt], bf);
            }
        }

        float tmax0 = -INFINITY, tmax1 = -INFINITY;
        #pragma unroll
        for (int nt = 0; nt < 8; nt++) {
            const int j0 = jt * 64 + nt * 8 + 2 * t4;
            const int mk0 = mkp[nt * 8 + 2 * t4];
            const int mk1 = mkp[nt * 8 + 2 * t4 + 1];
            float s0 = S[nt][0] * SCALE + rel_s[irow0 - j0 + (MAXSEQ - 1)];
            float s1 = S[nt][1] * SCALE + rel_s[irow0 - j0 - 1 + (MAXSEQ - 1)];
            float s2 = S[nt][2] * SCALE + rel_s[irow1 - j0 + (MAXSEQ - 1)];
            float s3 = S[nt][3] * SCALE + rel_s[irow1 - j0 - 1 + (MAXSEQ - 1)];
            if (mi0 == 0 || mk0 == 0) s0 = -1e9f;
            if (mi0 == 0 || mk1 == 0) s1 = -1e9f;
            if (mi1 == 0 || mk0 == 0) s2 = -1e9f;
            if (mi1 == 0 || mk1 == 0) s3 = -1e9f;
            S[nt][0] = s0; S[nt][1] = s1; S[nt][2] = s2; S[nt][3] = s3;
            tmax0 = fmaxf(tmax0, fmaxf(s0, s1));
            tmax1 = fmaxf(tmax1, fmaxf(s2, s3));
        }
        tmax0 = fmaxf(tmax0, __shfl_xor_sync(0xffffffffu, tmax0, 1));
        tmax0 = fmaxf(tmax0, __shfl_xor_sync(0xffffffffu, tmax0, 2));
        tmax1 = fmaxf(tmax1, __shfl_xor_sync(0xffffffffu, tmax1, 1));
        tmax1 = fmaxf(tmax1, __shfl_xor_sync(0xffffffffu, tmax1, 2));

        const float mn0 = fmaxf(m0, tmax0);
        const float mn1 = fmaxf(m1, tmax1);
        const float sc0 = exp2f((m0 - mn0) * L2E);
        const float sc1 = exp2f((m1 - mn1) * L2E);
        m0 = mn0; m1 = mn1;

        float ts0 = 0.0f, ts1 = 0.0f;
        #pragma unroll
        for (int nt = 0; nt < 8; nt++) {
            S[nt][0] = exp2f((S[nt][0] - mn0) * L2E);
            S[nt][1] = exp2f((S[nt][1] - mn0) * L2E);
            S[nt][2] = exp2f((S[nt][2] - mn1) * L2E);
            S[nt][3] = exp2f((S[nt][3] - mn1) * L2E);
            ts0 += S[nt][0] + S[nt][1];
            ts1 += S[nt][2] + S[nt][3];
        }
        ts0 += __shfl_xor_sync(0xffffffffu, ts0, 1);
        ts0 += __shfl_xor_sync(0xffffffffu, ts0, 2);
        ts1 += __shfl_xor_sync(0xffffffffu, ts1, 1);
        ts1 += __shfl_xor_sync(0xffffffffu, ts1, 2);
        l0 = l0 * sc0 + ts0;
        l1 = l1 * sc1 + ts1;

        const float scA = __shfl_sync(0xffffffffu, sc0, 8 * t4);
        const float scB = __shfl_sync(0xffffffffu, sc0, 8 * t4 + 4);
        const float scC = __shfl_sync(0xffffffffu, sc1, 8 * t4);
        const float scD = __shfl_sync(0xffffffffu, sc1, 8 * t4 + 4);
        #pragma unroll
        for (int mi = 0; mi < 4; mi++) {
            OcT[mi][0][0] *= scA; OcT[mi][0][1] *= scB;
            OcT[mi][0][2] *= scA; OcT[mi][0][3] *= scB;
            OcT[mi][1][0] *= scC; OcT[mi][1][1] *= scD;
            OcT[mi][1][2] *= scC; OcT[mi][1][3] *= scD;
        }

        #pragma unroll
        for (int kt = 0; kt < 8; kt++) {
            uint32_t b0t[2] = { f2tf(S[kt][0]), f2tf(S[kt][1]) };
            uint32_t b1t[2] = { f2tf(S[kt][2]), f2tf(S[kt][3]) };
            const uint32_t* vr0 = &Vs[(kt * 8 + 2 * t4) * VST];
            const uint32_t* vr1 = vr0 + VST;
            #pragma unroll
            for (int mi = 0; mi < 4; mi++) {
                const int d0 = mi * 16 + g;
                uint32_t a[4];
                a[0] = vr0[d0];
                a[1] = vr0[d0 + 8];
                a[2] = vr1[d0];
                a[3] = vr1[d0 + 8];
                mma_tf32(OcT[mi][0], a, b0t);
                mma_tf32(OcT[mi][1], a, b1t);
            }
        }
    }

    const float inv0 = 1.0f / l0;
    const float inv1 = 1.0f / l1;
    const float iA = __shfl_sync(0xffffffffu, inv0, 8 * t4);
    const float iB = __shfl_sync(0xffffffffu, inv0, 8 * t4 + 4);
    const float iC = __shfl_sync(0xffffffffu, inv1, 8 * t4);
    const float iD = __shfl_sync(0xffffffffu, inv1, 8 * t4 + 4);
    #pragma unroll
    for (int mi = 0; mi < 4; mi++) {
        const int col = h * HDIM + mi * 16 + g;
        #pragma unroll
        for (int ni = 0; ni < 2; ni++) {
            const int r0 = i0 + w * 16 + ni * 8 + 2 * t4;
            const float f0 = ni ? iC : iA;
            const float f1 = ni ? iD : iB;
            float* c0 = ctx + (size_t)(b * NSEQ + r0) * BDIM + col;
            float* c1 = ctx + (size_t)(b * NSEQ + r0 + 1) * BDIM + col;
            c0[0] = f2tff(OcT[mi][ni][0] * f0);
            c1[0] = f2tff(OcT[mi][ni][1] * f1);
            c0[8] = f2tff(OcT[mi][ni][2] * f0);
            c1[8] = f2tff(OcT[mi][ni][3] * f1);
        }
    }
}

// ---------------- launch ----------------
extern "C" void kernel_launch(void* const* d_in, const int* in_sizes, int n_in,
                              void* d_out, int out_size)
{
    const float* x      = (const float*)d_in[0];
    const int*   mask   = (const int*)  d_in[1];
    const float* ln1_g  = (const float*)d_in[2];
    const float* ln1_b  = (const float*)d_in[3];
    const float* qkv_w  = (const float*)d_in[4];
    const float* qkv_b  = (const float*)d_in[5];
    const float* proj_w = (const float*)d_in[6];
    const float* proj_b = (const float*)d_in[7];
    const float* rel    = (const float*)d_in[8];
    const float* ln2_g  = (const float*)d_in[9];
    const float* ln2_b  = (const float*)d_in[10];
    const float* w1     = (const float*)d_in[11];
    const float* b1     = (const float*)d_in[12];
    const float* w2     = (const float*)d_in[13];
    const float* b2     = (const float*)d_in[14];
    const float* gate1  = (const float*)d_in[15];
    const float* gate2  = (const float*)d_in[16];
    float* out = (float*)d_out;

    float *xn, *qkv, *ctx, *y, *mlp, *qkvw, *projw, *w1t, *w2t;
    cudaGetSymbolAddress((void**)&xn,    g_xn);
    cudaGetSymbolAddress((void**)&qkv,   g_qkv);
    cudaGetSymbolAddress((void**)&ctx,   g_ctx);
    cudaGetSymbolAddress((void**)&y,     g_y);
    cudaGetSymbolAddress((void**)&mlp,   g_mlp);
    cudaGetSymbolAddress((void**)&qkvw,  g_qkvw);
    cudaGetSymbolAddress((void**)&projw, g_projw);
    cudaGetSymbolAddress((void**)&w1t,   g_w1);
    cudaGetSymbolAddress((void**)&w2t,   g_w2);

    static bool attr_set = false;
    if (!attr_set) {
        cudaFuncSetAttribute(tf32gemm_kernel<EPI_BIAS>,
                             cudaFuncAttributeMaxDynamicSharedMemorySize, GEMM_SMEM);
        cudaFuncSetAttribute(tf32gemm_kernel<EPI_GELU>,
                             cudaFuncAttributeMaxDynamicSharedMemorySize, GEMM_SMEM);
        cudaFuncSetAttribute(tf32gemm_kernel<EPI_RESGATE>,
                             cudaFuncAttributeMaxDynamicSharedMemorySize, GEMM_SMEM);
        cudaFuncSetAttribute(flash_attn_kernel,
                             cudaFuncAttributeMaxDynamicSharedMemorySize, FL_SMEM);
        attr_set = true;
    }

    // 0) transpose + tf32-round weights -> [N, K] K-major
    transpose_tf32_kernel<<<dim3(3*BDIM/32, BDIM/32), 256>>>(qkv_w, qkvw, BDIM, 3*BDIM);
    transpose_tf32_kernel<<<dim3(BDIM/32,   BDIM/32), 256>>>(proj_w, projw, BDIM, BDIM);
    transpose_tf32_kernel<<<dim3(4*BDIM/32, BDIM/32), 256>>>(w1, w1t, BDIM, 4*BDIM);
    transpose_tf32_kernel<<<dim3(BDIM/32, 4*BDIM/32), 256>>>(w2, w2t, 4*BDIM, BDIM);

    // 1) LN1 (tf32-rounded output)
    ln_kernel<<<ROWS / 8, 256>>>(x, ln1_g, ln1_b, xn);
    // 2) qkv = xn @ qkv_w + qkv_b (output tf32-rounded for flash)
    tf32gemm_kernel<EPI_BIAS><<<dim3(3 * BDIM / 128, ROWS / 128), 256, GEMM_SMEM>>>(
        xn, qkvw, qkv_b, nullptr, nullptr, qkv, ROWS, 3 * BDIM, BDIM);
    // 3) fused attention -> ctx (tf32-rounded)
    flash_attn_kernel<<<dim3(NSEQ / 128, NB * NHEADS), 256, FL_SMEM>>>(qkv, mask, rel, ctx);
    // 4) y = x + gate1 * (ctx @ proj_w + proj_b)
    tf32gemm_kernel<EPI_RESGATE><<<dim3(BDIM / 128, ROWS / 128), 256, GEMM_SMEM>>>(
        ctx, projw, proj_b, x, gate1, y, ROWS, BDIM, BDIM);
    // 5) LN2 (tf32-rounded output)
    ln_kernel<<<ROWS / 8, 256>>>(y, ln2_g, ln2_b, xn);
    // 6) mlp = gelu(xn @ w1 + b1) (tf32-rounded)
    tf32gemm_kernel<EPI_GELU><<<dim3(4 * BDIM / 128, ROWS / 128), 256, GEMM_SMEM>>>(
        xn, w1t, b1, nullptr, nullptr, mlp, ROWS, 4 * BDIM, BDIM);
    // 7) out = y + gate2 * (mlp @ w2 + b2)
    tf32gemm_kernel<EPI_RESGATE><<<dim3(BDIM / 128, ROWS / 128), 256, GEMM_SMEM>>>(
        mlp, w2t, b2, y, gate2, out, ROWS, BDIM, 4 * BDIM);
}

// round 12
// speedup vs baseline: 1.6490x; 1.6490x over previous
#include <cuda_runtime.h>
#include <cuda_fp16.h>
#include <math.h>
#include <stdint.h>

#define BDIM 1024
#define NB 4
#define NSEQ 1024
#define NHEADS 16
#define HDIM 64
#define ROWS (NB*NSEQ)   // 4096
#define MAXSEQ 1024

// ---------------- scratch (device globals; no allocation allowed) ----------------
__device__ __half g_xn[(size_t)ROWS*BDIM];              // 8 MB (fp16 LN out)
__device__ float  g_qkv[(size_t)ROWS*3*BDIM];           // 48 MB (f32, tf32-rounded, for flash)
__device__ __half g_ctx[(size_t)ROWS*BDIM];             // 8 MB (fp16)
__device__ float  g_y[(size_t)ROWS*BDIM];               // 16 MB
__device__ __half g_mlp[(size_t)ROWS*4*BDIM];           // 32 MB (fp16 gelu out)
// fp16 TRANSPOSED weights [N, K] K-major
__device__ __half g_qkvw[(size_t)BDIM*3*BDIM];          // 6 MB
__device__ __half g_projw[(size_t)BDIM*BDIM];           // 2 MB
__device__ __half g_w1[(size_t)BDIM*4*BDIM];            // 8 MB
__device__ __half g_w2[(size_t)4*BDIM*BDIM];            // 8 MB

// ---------------- helpers ----------------
__device__ __forceinline__ uint32_t f2tf(float x) {
    uint32_t r;
    asm("cvt.rna.tf32.f32 %0, %1;" : "=r"(r) : "f"(x));
    return r;
}
__device__ __forceinline__ float f2tff(float x) { return __uint_as_float(f2tf(x)); }

__device__ __forceinline__ void mma_tf32(float c[4], const uint32_t a[4], const uint32_t b[2]) {
    asm volatile(
        "mma.sync.aligned.m16n8k8.row.col.f32.tf32.tf32.f32 "
        "{%0,%1,%2,%3}, {%4,%5,%6,%7}, {%8,%9}, {%0,%1,%2,%3};"
        : "+f"(c[0]), "+f"(c[1]), "+f"(c[2]), "+f"(c[3])
        : "r"(a[0]), "r"(a[1]), "r"(a[2]), "r"(a[3]), "r"(b[0]), "r"(b[1]));
}

__device__ __forceinline__ void mma_f16(float c[4], const uint32_t a[4], const uint32_t b[2]) {
    asm volatile(
        "mma.sync.aligned.m16n8k16.row.col.f32.f16.f16.f32 "
        "{%0,%1,%2,%3}, {%4,%5,%6,%7}, {%8,%9}, {%0,%1,%2,%3};"
        : "+f"(c[0]), "+f"(c[1]), "+f"(c[2]), "+f"(c[3])
        : "r"(a[0]), "r"(a[1]), "r"(a[2]), "r"(a[3]), "r"(b[0]), "r"(b[1]));
}

__device__ __forceinline__ void cp_async16(uint32_t smem_addr, const void* gptr) {
    asm volatile("cp.async.cg.shared.global [%0], [%1], 16;"
                 :: "r"(smem_addr), "l"(gptr));
}
__device__ __forceinline__ void cp_commit() { asm volatile("cp.async.commit_group;"); }
template<int N>
__device__ __forceinline__ void cp_wait() { asm volatile("cp.async.wait_group %0;" :: "n"(N)); }

// ---------------- weight transpose + fp16 round: out[n*K+k] = half(in[k*N+n]) ----------------
__global__ __launch_bounds__(256) void transpose_h_kernel(
    const float* __restrict__ in, __half* __restrict__ out, int K, int N)
{
    __shared__ float t[32][33];
    const int n0 = blockIdx.x * 32, k0 = blockIdx.y * 32;
    const int tx = threadIdx.x & 31, ty = threadIdx.x >> 5;  // 32 x 8
    #pragma unroll
    for (int i = 0; i < 32; i += 8)
        t[ty + i][tx] = in[(size_t)(k0 + ty + i) * N + n0 + tx];
    __syncthreads();
    #pragma unroll
    for (int i = 0; i < 32; i += 8)
        out[(size_t)(n0 + ty + i) * K + k0 + tx] = __float2half_rn(t[tx][ty + i]);
}

// ---------------- LayerNorm: warp per row; fp16 output ----------------
__global__ __launch_bounds__(256) void ln_kernel(const float* __restrict__ x,
    const float* __restrict__ g, const float* __restrict__ b, __half* __restrict__ out)
{
    const int row  = blockIdx.x * 8 + (threadIdx.x >> 5);
    const int lane = threadIdx.x & 31;
    const float4* xr = reinterpret_cast<const float4*>(x + (size_t)row * BDIM);
    float4 v[8];
    float s = 0.0f;
    #pragma unroll
    for (int i = 0; i < 8; i++) {
        v[i] = xr[lane + 32 * i];
        s += v[i].x + v[i].y + v[i].z + v[i].w;
    }
    #pragma unroll
    for (int o = 16; o > 0; o >>= 1) s += __shfl_xor_sync(0xffffffffu, s, o);
    const float mu = s * (1.0f / BDIM);
    float q = 0.0f;
    #pragma unroll
    for (int i = 0; i < 8; i++) {
        v[i].x -= mu; v[i].y -= mu; v[i].z -= mu; v[i].w -= mu;
        q += v[i].x*v[i].x + v[i].y*v[i].y + v[i].z*v[i].z + v[i].w*v[i].w;
    }
    #pragma unroll
    for (int o = 16; o > 0; o >>= 1) q += __shfl_xor_sync(0xffffffffu, q, o);
    const float rinv = rsqrtf(q * (1.0f / BDIM) + 1e-5f);
    __half* orow = out + (size_t)row * BDIM;
    #pragma unroll
    for (int i = 0; i < 8; i++) {
        float4 gg = reinterpret_cast<const float4*>(g)[lane + 32 * i];
        float4 bb = reinterpret_cast<const float4*>(b)[lane + 32 * i];
        __half2 h01 = __floats2half2_rn(v[i].x * rinv * gg.x + bb.x,
                                        v[i].y * rinv * gg.y + bb.y);
        __half2 h23 = __floats2half2_rn(v[i].z * rinv * gg.z + bb.z,
                                        v[i].w * rinv * gg.w + bb.w);
        uint2 u = { *reinterpret_cast<uint32_t*>(&h01), *reinterpret_cast<uint32_t*>(&h23) };
        *reinterpret_cast<uint2*>(orow + (lane + 32 * i) * 4) = u;
    }
}

// ---------------- 3-stage cp.async FP16 GEMM: 128 threads, warp 64x64 ----------------
// A[M,K], Wt[N,K] fp16 K-major; 128B rows (BK=64), XOR swizzle (row&3)<<5.
// Per k16-chunk per warp: 32 HMMA(k16) : 16 LDS.64 -> 64 B/HMMA. 2 CTAs/SM.
enum { EPI_BIAS = 0, EPI_GELU = 1, EPI_RESGATE = 2 };

#define FSTAGES 3
#define FSTAGE_B 32768                 // A 16KB + B 16KB per stage
#define GEMM_SMEM (FSTAGES*FSTAGE_B)   // 98304 bytes

template<int EPI>
__global__ __launch_bounds__(128) void h16gemm_kernel(
    const __half* __restrict__ A, const __half* __restrict__ Wt,
    const float* __restrict__ bias, const float* __restrict__ res,
    const float* __restrict__ gate, void* __restrict__ Cv,
    int M, int N, int K)
{
    constexpr int BK = 64;
    extern __shared__ uint32_t sm[];
    const uint32_t sm_u = (uint32_t)__cvta_generic_to_shared(sm);

    const int tid  = threadIdx.x;
    const int lane = tid & 31;
    const int wid  = tid >> 5;
    const int g    = lane >> 2;
    const int t4   = lane & 3;
    const int mWarp = (wid >> 1) * 64;    // 0 or 64
    const int nWarp = (wid & 1) * 64;     // 0 or 64

    // global->smem: thread covers rows lrow, lrow+16, ..., chunk lchunk (16B)
    const int lrow   = tid >> 3;          // 0..15
    const int lchunk = tid & 7;           // 0..7
    const uint32_t swb = (uint32_t)((lchunk * 16) ^ ((lrow & 3) << 5));

    const __half* Ap = A  + (size_t)(blockIdx.y * 128 + lrow) * K + lchunk * 8;
    const __half* Bp = Wt + (size_t)(blockIdx.x * 128 + lrow) * K + lchunk * 8;

    const int nT = K / BK;

    // prologue: stages 0,1
    #pragma unroll
    for (int t = 0; t < FSTAGES - 1; t++) {
        const uint32_t ab = sm_u + t * FSTAGE_B;
        #pragma unroll
        for (int p = 0; p < 8; p++) {
            cp_async16(ab + (uint32_t)((lrow + p * 16) * 128) + swb,
                       Ap + (size_t)t * BK + (size_t)(p * 16) * K);
            cp_async16(ab + 16384u + (uint32_t)((lrow + p * 16) * 128) + swb,
                       Bp + (size_t)t * BK + (size_t)(p * 16) * K);
        }
        cp_commit();
    }

    float acc[4][8][4] = {};

    for (int t = 0; t < nT; t++) {
        cp_wait<FSTAGES - 2>();
        __syncthreads();

        const int tn = t + FSTAGES - 1;
        if (tn < nT) {
            int sl = tn % FSTAGES;
            const uint32_t ab = sm_u + sl * FSTAGE_B;
            #pragma unroll
            for (int p = 0; p < 8; p++) {
                cp_async16(ab + (uint32_t)((lrow + p * 16) * 128) + swb,
                           Ap + (size_t)tn * BK + (size_t)(p * 16) * K);
                cp_async16(ab + 16384u + (uint32_t)((lrow + p * 16) * 128) + swb,
                           Bp + (size_t)tn * BK + (size_t)(p * 16) * K);
            }
        }
        cp_commit();

        const uint32_t aB = sm_u + (t % FSTAGES) * FSTAGE_B;
        const uint32_t bB = aB + 16384u;
        const uint32_t gsw = (uint32_t)((g & 3) << 5);
        #pragma unroll
        for (int kc = 0; kc < 4; kc++) {
            const uint32_t koff = (uint32_t)((kc * 32 + 8 * t4)) ^ gsw;
            uint32_t bf[8][2];
            #pragma unroll
            for (int ni = 0; ni < 8; ni++) {
                uint2 bb;
                asm volatile("ld.shared.v2.b32 {%0,%1}, [%2];"
                             : "=r"(bb.x), "=r"(bb.y)
                             : "r"(bB + (uint32_t)((nWarp + ni * 8 + g) * 128) + koff));
                bf[ni][0] = bb.x; bf[ni][1] = bb.y;
            }
            #pragma unroll
            for (int mi = 0; mi < 4; mi++) {
                const int mb = mWarp + mi * 16;
                uint2 a0, a1;
                asm volatile("ld.shared.v2.b32 {%0,%1}, [%2];"
                             : "=r"(a0.x), "=r"(a0.y)
                             : "r"(aB + (uint32_t)((mb + g) * 128) + koff));
                asm volatile("ld.shared.v2.b32 {%0,%1}, [%2];"
                             : "=r"(a1.x), "=r"(a1.y)
                             : "r"(aB + (uint32_t)((mb + g + 8) * 128) + koff));
                uint32_t af[4] = { a0.x, a1.x, a0.y, a1.y };
                #pragma unroll
                for (int ni = 0; ni < 8; ni++)
                    mma_f16(acc[mi][ni], af, bf[ni]);
            }
        }
    }

    // epilogue
    const float gt = (EPI == EPI_RESGATE) ? gate[0] : 0.0f;
    #pragma unroll
    for (int mi = 0; mi < 4; mi++) {
        const int row0 = blockIdx.y * 128 + mWarp + mi * 16 + g;
        #pragma unroll
        for (int ni = 0; ni < 8; ni++) {
            const int col = blockIdx.x * 128 + nWarp + ni * 8 + t4 * 2;
            const float b0 = bias[col], b1 = bias[col + 1];
            #pragma unroll
            for (int h = 0; h < 2; h++) {
                const int row = row0 + h * 8;
                float v0 = acc[mi][ni][2 * h + 0] + b0;
                float v1 = acc[mi][ni][2 * h + 1] + b1;
                if (EPI == EPI_BIAS) {   // qkv: f32 out, tf32-rounded for flash
                    float* C = (float*)Cv;
                    *reinterpret_cast<float2*>(C + (size_t)row * N + col) =
                        make_float2(f2tff(v0), f2tff(v1));
                }
                if (EPI == EPI_GELU) {   // fp16 out
                    v0 = 0.5f * v0 * (1.0f + erff(v0 * 0.70710678118654752f));
                    v1 = 0.5f * v1 * (1.0f + erff(v1 * 0.70710678118654752f));
                    __half2 hv = __floats2half2_rn(v0, v1);
                    *reinterpret_cast<uint32_t*>((__half*)Cv + (size_t)row * N + col) =
                        *reinterpret_cast<uint32_t*>(&hv);
                }
                if (EPI == EPI_RESGATE) {
                    float* C = (float*)Cv;
                    const size_t off = (size_t)row * N + col;
                    *reinterpret_cast<float2*>(C + off) =
                        make_float2(res[off] + gt * v0, res[off + 1] + gt * v1);
                }
            }
        }
    }
}

// ---------------- Fused flash attention (TF32; O^T form; cp.async K/V pipeline) ----------------
#define KST 72
#define VST 76
#define FL_SLOTW (64*KST + 64*VST)
#define FL_MK    (2*FL_SLOTW)
#define FL_REL   (FL_MK + 128)
#define FL_WORDS (FL_REL + 2048)
#define FL_SMEM  (FL_WORDS*4)

__global__ __launch_bounds__(256, 2) void flash_attn_kernel(
    const float* __restrict__ qkv, const int* __restrict__ mask,
    const float* __restrict__ rel, __half* __restrict__ ctx)
{
    constexpr float SCALE = 0.125f;
    constexpr float L2E = 1.4426950408889634f;

    extern __shared__ __align__(16) uint32_t sm[];
    const uint32_t sm_u = (uint32_t)__cvta_generic_to_shared(sm);
    const int* mki  = reinterpret_cast<const int*>(sm + FL_MK);
    float* rel_s    = reinterpret_cast<float*>(sm + FL_REL);
    uint32_t* Qst   = sm + FL_SLOTW;

    const int bh = blockIdx.y;
    const int b = bh >> 4, h = bh & 15;
    const int i0 = blockIdx.x * 128;
    const int tid = threadIdx.x, lane = tid & 31, w = tid >> 5;
    const int g = lane >> 2, t4 = lane & 3;

    const int ldr = tid >> 2;
    const int ldc = (tid & 3) * 16;
    const float* kvbase = qkv + (size_t)(b * NSEQ + ldr) * (3 * BDIM) + BDIM + h * HDIM + ldc;

    {
        const float* kp = kvbase;
        const uint32_t kdst = sm_u + (uint32_t)(ldr * KST + ldc) * 4;
        const uint32_t vdst = sm_u + (uint32_t)(64 * KST + ldr * VST + ldc) * 4;
        #pragma unroll
        for (int i = 0; i < 4; i++) {
            cp_async16(kdst + 16 * i, kp + 4 * i);
            cp_async16(vdst + 16 * i, kp + BDIM + 4 * i);
        }
        if (tid < 16)
            cp_async16(sm_u + (uint32_t)(FL_MK + tid * 4) * 4, mask + b * NSEQ + tid * 4);
        cp_commit();
    }

    for (int idx = tid; idx < 2 * MAXSEQ - 1; idx += 256)
        rel_s[idx] = rel[(size_t)idx * NHEADS + h];

    {
        const int r = tid >> 1;
        const int c0 = (tid & 1) * 32;
        const float* qp = qkv + ((size_t)(b * NSEQ + i0 + r)) * (3 * BDIM) + h * HDIM + c0;
        #pragma unroll
        for (int i = 0; i < 8; i++)
            *reinterpret_cast<uint4*>(&Qst[r * KST + c0 + 4 * i]) =
                *reinterpret_cast<const uint4*>(qp + 4 * i);
    }
    __syncthreads();

    uint32_t Qa[8][4];
    #pragma unroll
    for (int kt = 0; kt < 8; kt++) {
        uint2 q0 = *reinterpret_cast<const uint2*>(&Qst[(w * 16 + g) * KST + kt * 8 + 2 * t4]);
        uint2 q1 = *reinterpret_cast<const uint2*>(&Qst[(w * 16 + g + 8) * KST + kt * 8 + 2 * t4]);
        Qa[kt][0] = q0.x; Qa[kt][1] = q1.x; Qa[kt][2] = q0.y; Qa[kt][3] = q1.y;
    }

    const int irow0 = i0 + w * 16 + g;
    const int irow1 = irow0 + 8;
    const int mi0 = mask[b * NSEQ + irow0];
    const int mi1 = mask[b * NSEQ + irow1];

    float m0 = -INFINITY, m1 = -INFINITY, l0 = 0.0f, l1 = 0.0f;
    float OcT[4][2][4] = {};

    for (int jt = 0; jt < NSEQ / 64; jt++) {
        cp_wait<0>();
        __syncthreads();

        if (jt + 1 < NSEQ / 64) {
            const int ns = (jt + 1) & 1;
            const float* kp = kvbase + (size_t)(jt + 1) * 64 * (3 * BDIM);
            const uint32_t kdst = sm_u + (uint32_t)(ns * FL_SLOTW + ldr * KST + ldc) * 4;
            const uint32_t vdst = sm_u + (uint32_t)(ns * FL_SLOTW + 64 * KST + ldr * VST + ldc) * 4;
            #pragma unroll
            for (int i = 0; i < 4; i++) {
                cp_async16(kdst + 16 * i, kp + 4 * i);
                cp_async16(vdst + 16 * i, kp + BDIM + 4 * i);
            }
            if (tid < 16)
                cp_async16(sm_u + (uint32_t)(FL_MK + ns * 64 + tid * 4) * 4,
                           mask + b * NSEQ + (jt + 1) * 64 + tid * 4);
            cp_commit();
        }

        const int slot = jt & 1;
        const uint32_t* Ks = sm + slot * FL_SLOTW;
        const uint32_t* Vs = sm + slot * FL_SLOTW + 64 * KST;
        const int* mkp = mki + slot * 64;

        float S[8][4] = {};
        #pragma unroll
        for (int nt = 0; nt < 8; nt++) {
            #pragma unroll
            for (int kt = 0; kt < 8; kt++) {
                uint2 kk = *reinterpret_cast<const uint2*>(&Ks[(nt * 8 + g) * KST + kt * 8 + 2 * t4]);
                uint32_t bf[2] = { kk.x, kk.y };
                mma_tf32(S[nt], Qa[kt], bf);
            }
        }

        float tmax0 = -INFINITY, tmax1 = -INFINITY;
        #pragma unroll
        for (int nt = 0; nt < 8; nt++) {
            const int j0 = jt * 64 + nt * 8 + 2 * t4;
            const int mk0 = mkp[nt * 8 + 2 * t4];
            const int mk1 = mkp[nt * 8 + 2 * t4 + 1];
            float s0 = S[nt][0] * SCALE + rel_s[irow0 - j0 + (MAXSEQ - 1)];
            float s1 = S[nt][1] * SCALE + rel_s[irow0 - j0 - 1 + (MAXSEQ - 1)];
            float s2 = S[nt][2] * SCALE + rel_s[irow1 - j0 + (MAXSEQ - 1)];
            float s3 = S[nt][3] * SCALE + rel_s[irow1 - j0 - 1 + (MAXSEQ - 1)];
            if (mi0 == 0 || mk0 == 0) s0 = -1e9f;
            if (mi0 == 0 || mk1 == 0) s1 = -1e9f;
            if (mi1 == 0 || mk0 == 0) s2 = -1e9f;
            if (mi1 == 0 || mk1 == 0) s3 = -1e9f;
            S[nt][0] = s0; S[nt][1] = s1; S[nt][2] = s2; S[nt][3] = s3;
            tmax0 = fmaxf(tmax0, fmaxf(s0, s1));
            tmax1 = fmaxf(tmax1, fmaxf(s2, s3));
        }
        tmax0 = fmaxf(tmax0, __shfl_xor_sync(0xffffffffu, tmax0, 1));
        tmax0 = fmaxf(tmax0, __shfl_xor_sync(0xffffffffu, tmax0, 2));
        tmax1 = fmaxf(tmax1, __shfl_xor_sync(0xffffffffu, tmax1, 1));
        tmax1 = fmaxf(tmax1, __shfl_xor_sync(0xffffffffu, tmax1, 2));

        const float mn0 = fmaxf(m0, tmax0);
        const float mn1 = fmaxf(m1, tmax1);
        const float sc0 = exp2f((m0 - mn0) * L2E);
        const float sc1 = exp2f((m1 - mn1) * L2E);
        m0 = mn0; m1 = mn1;

        float ts0 = 0.0f, ts1 = 0.0f;
        #pragma unroll
        for (int nt = 0; nt < 8; nt++) {
            S[nt][0] = exp2f((S[nt][0] - mn0) * L2E);
            S[nt][1] = exp2f((S[nt][1] - mn0) * L2E);
            S[nt][2] = exp2f((S[nt][2] - mn1) * L2E);
            S[nt][3] = exp2f((S[nt][3] - mn1) * L2E);
            ts0 += S[nt][0] + S[nt][1];
            ts1 += S[nt][2] + S[nt][3];
        }
        ts0 += __shfl_xor_sync(0xffffffffu, ts0, 1);
        ts0 += __shfl_xor_sync(0xffffffffu, ts0, 2);
        ts1 += __shfl_xor_sync(0xffffffffu, ts1, 1);
        ts1 += __shfl_xor_sync(0xffffffffu, ts1, 2);
        l0 = l0 * sc0 + ts0;
        l1 = l1 * sc1 + ts1;

        const float scA = __shfl_sync(0xffffffffu, sc0, 8 * t4);
        const float scB = __shfl_sync(0xffffffffu, sc0, 8 * t4 + 4);
        const float scC = __shfl_sync(0xffffffffu, sc1, 8 * t4);
        const float scD = __shfl_sync(0xffffffffu, sc1, 8 * t4 + 4);
        #pragma unroll
        for (int mi = 0; mi < 4; mi++) {
            OcT[mi][0][0] *= scA; OcT[mi][0][1] *= scB;
            OcT[mi][0][2] *= scA; OcT[mi][0][3] *= scB;
            OcT[mi][1][0] *= scC; OcT[mi][1][1] *= scD;
            OcT[mi][1][2] *= scC; OcT[mi][1][3] *= scD;
        }

        #pragma unroll
        for (int kt = 0; kt < 8; kt++) {
            uint32_t b0t[2] = { f2tf(S[kt][0]), f2tf(S[kt][1]) };
            uint32_t b1t[2] = { f2tf(S[kt][2]), f2tf(S[kt][3]) };
            const uint32_t* vr0 = &Vs[(kt * 8 + 2 * t4) * VST];
            const uint32_t* vr1 = vr0 + VST;
            #pragma unroll
            for (int mi = 0; mi < 4; mi++) {
                const int d0 = mi * 16 + g;
                uint32_t a[4];
                a[0] = vr0[d0];
                a[1] = vr0[d0 + 8];
                a[2] = vr1[d0];
                a[3] = vr1[d0 + 8];
                mma_tf32(OcT[mi][0], a, b0t);
                mma_tf32(OcT[mi][1], a, b1t);
            }
        }
    }

    // writeback ctx = O / l -> fp16 (feeds proj GEMM)
    const float inv0 = 1.0f / l0;
    const float inv1 = 1.0f / l1;
    const float iA = __shfl_sync(0xffffffffu, inv0, 8 * t4);
    const float iB = __shfl_sync(0xffffffffu, inv0, 8 * t4 + 4);
    const float iC = __shfl_sync(0xffffffffu, inv1, 8 * t4);
    const float iD = __shfl_sync(0xffffffffu, inv1, 8 * t4 + 4);
    #pragma unroll
    for (int mi = 0; mi < 4; mi++) {
        const int col = h * HDIM + mi * 16 + g;
        #pragma unroll
        for (int ni = 0; ni < 2; ni++) {
            const int r0 = i0 + w * 16 + ni * 8 + 2 * t4;
            const float f0 = ni ? iC : iA;
            const float f1 = ni ? iD : iB;
            __half* c0 = ctx + (size_t)(b * NSEQ + r0) * BDIM + col;
            __half* c1 = ctx + (size_t)(b * NSEQ + r0 + 1) * BDIM + col;
            c0[0] = __float2half_rn(OcT[mi][ni][0] * f0);
            c1[0] = __float2half_rn(OcT[mi][ni][1] * f1);
            c0[8] = __float2half_rn(OcT[mi][ni][2] * f0);
            c1[8] = __float2half_rn(OcT[mi][ni][3] * f1);
        }
    }
}

// ---------------- launch ----------------
extern "C" void kernel_launch(void* const* d_in, const int* in_sizes, int n_in,
                              void* d_out, int out_size)
{
    const float* x      = (const float*)d_in[0];
    const int*   mask   = (const int*)  d_in[1];
    const float* ln1_g  = (const float*)d_in[2];
    const float* ln1_b  = (const float*)d_in[3];
    const float* qkv_w  = (const float*)d_in[4];
    const float* qkv_b  = (const float*)d_in[5];
    const float* proj_w = (const float*)d_in[6];
    const float* proj_b = (const float*)d_in[7];
    const float* rel    = (const float*)d_in[8];
    const float* ln2_g  = (const float*)d_in[9];
    const float* ln2_b  = (const float*)d_in[10];
    const float* w1     = (const float*)d_in[11];
    const float* b1     = (const float*)d_in[12];
    const float* w2     = (const float*)d_in[13];
    const float* b2     = (const float*)d_in[14];
    const float* gate1  = (const float*)d_in[15];
    const float* gate2  = (const float*)d_in[16];
    float* out = (float*)d_out;

    __half *xn, *ctx, *mlp, *qkvw, *projw, *w1t, *w2t;
    float *qkv, *y;
    cudaGetSymbolAddress((void**)&xn,    g_xn);
    cudaGetSymbolAddress((void**)&qkv,   g_qkv);
    cudaGetSymbolAddress((void**)&ctx,   g_ctx);
    cudaGetSymbolAddress((void**)&y,     g_y);
    cudaGetSymbolAddress((void**)&mlp,   g_mlp);
    cudaGetSymbolAddress((void**)&qkvw,  g_qkvw);
    cudaGetSymbolAddress((void**)&projw, g_projw);
    cudaGetSymbolAddress((void**)&w1t,   g_w1);
    cudaGetSymbolAddress((void**)&w2t,   g_w2);

    static bool attr_set = false;
    if (!attr_set) {
        cudaFuncSetAttribute(h16gemm_kernel<EPI_BIAS>,
                             cudaFuncAttributeMaxDynamicSharedMemorySize, GEMM_SMEM);
        cudaFuncSetAttribute(h16gemm_kernel<EPI_GELU>,
                             cudaFuncAttributeMaxDynamicSharedMemorySize, GEMM_SMEM);
        cudaFuncSetAttribute(h16gemm_kernel<EPI_RESGATE>,
                             cudaFuncAttributeMaxDynamicSharedMemorySize, GEMM_SMEM);
        cudaFuncSetAttribute(flash_attn_kernel,
                             cudaFuncAttributeMaxDynamicSharedMemorySize, FL_SMEM);
        attr_set = true;
    }

    // 0) transpose + fp16-round weights -> [N, K] K-major
    transpose_h_kernel<<<dim3(3*BDIM/32, BDIM/32), 256>>>(qkv_w, qkvw, BDIM, 3*BDIM);
    transpose_h_kernel<<<dim3(BDIM/32,   BDIM/32), 256>>>(proj_w, projw, BDIM, BDIM);
    transpose_h_kernel<<<dim3(4*BDIM/32, BDIM/32), 256>>>(w1, w1t, BDIM, 4*BDIM);
    transpose_h_kernel<<<dim3(BDIM/32, 4*BDIM/32), 256>>>(w2, w2t, 4*BDIM, BDIM);

    // 1) LN1 -> fp16
    ln_kernel<<<ROWS / 8, 256>>>(x, ln1_g, ln1_b, xn);
    // 2) qkv = xn @ qkv_w + qkv_b (f32 out, tf32-rounded for flash)
    h16gemm_kernel<EPI_BIAS><<<dim3(3 * BDIM / 128, ROWS / 128), 128, GEMM_SMEM>>>(
        xn, qkvw, qkv_b, nullptr, nullptr, qkv, ROWS, 3 * BDIM, BDIM);
    // 3) fused attention -> ctx (fp16)
    flash_attn_kernel<<<dim3(NSEQ / 128, NB * NHEADS), 256, FL_SMEM>>>(qkv, mask, rel, ctx);
    // 4) y = x + gate1 * (ctx @ proj_w + proj_b)
    h16gemm_kernel<EPI_RESGATE><<<dim3(BDIM / 128, ROWS / 128), 128, GEMM_SMEM>>>(
        ctx, projw, proj_b, x, gate1, y, ROWS, BDIM, BDIM);
    // 5) LN2 -> fp16
    ln_kernel<<<ROWS / 8, 256>>>(y, ln2_g, ln2_b, xn);
    // 6) mlp = gelu(xn @ w1 + b1) -> fp16
    h16gemm_kernel<EPI_GELU><<<dim3(4 * BDIM / 128, ROWS / 128), 128, GEMM_SMEM>>>(
        xn, w1t, b1, nullptr, nullptr, mlp, ROWS, 4 * BDIM, BDIM);
    // 7) out = y + gate2 * (mlp @ w2 + b2)
    h16gemm_kernel<EPI_RESGATE><<<dim3(BDIM / 128, ROWS / 128), 128, GEMM_SMEM>>>(
        mlp, w2t, b2, y, gate2, out, ROWS, BDIM, 4 * BDIM);
}

// round 13
// speedup vs baseline: 1.7944x; 1.0882x over previous
#include <cuda_runtime.h>
#include <cuda_fp16.h>
#include <math.h>
#include <stdint.h>

#define BDIM 1024
#define NB 4
#define NSEQ 1024
#define NHEADS 16
#define HDIM 64
#define ROWS (NB*NSEQ)   // 4096
#define MAXSEQ 1024

// ---------------- scratch (device globals; no allocation allowed) ----------------
__device__ __half g_xn[(size_t)ROWS*BDIM];              // 8 MB (fp16 LN out)
__device__ float  g_qkv[(size_t)ROWS*3*BDIM];           // 48 MB (only V third used, f32)
__device__ __half g_qkvh[(size_t)ROWS*2*BDIM];          // 16 MB (Q,K fp16)
__device__ __half g_ctx[(size_t)ROWS*BDIM];             // 8 MB (fp16)
__device__ float  g_y[(size_t)ROWS*BDIM];               // 16 MB
__device__ __half g_mlp[(size_t)ROWS*4*BDIM];           // 32 MB (fp16 gelu out)
// fp16 TRANSPOSED weights [N, K] K-major
__device__ __half g_qkvw[(size_t)BDIM*3*BDIM];          // 6 MB
__device__ __half g_projw[(size_t)BDIM*BDIM];           // 2 MB
__device__ __half g_w1[(size_t)BDIM*4*BDIM];            // 8 MB
__device__ __half g_w2[(size_t)4*BDIM*BDIM];            // 8 MB

// ---------------- helpers ----------------
__device__ __forceinline__ uint32_t f2tf(float x) {
    uint32_t r;
    asm("cvt.rna.tf32.f32 %0, %1;" : "=r"(r) : "f"(x));
    return r;
}
__device__ __forceinline__ float f2tff(float x) { return __uint_as_float(f2tf(x)); }

__device__ __forceinline__ void mma_tf32(float c[4], const uint32_t a[4], const uint32_t b[2]) {
    asm volatile(
        "mma.sync.aligned.m16n8k8.row.col.f32.tf32.tf32.f32 "
        "{%0,%1,%2,%3}, {%4,%5,%6,%7}, {%8,%9}, {%0,%1,%2,%3};"
        : "+f"(c[0]), "+f"(c[1]), "+f"(c[2]), "+f"(c[3])
        : "r"(a[0]), "r"(a[1]), "r"(a[2]), "r"(a[3]), "r"(b[0]), "r"(b[1]));
}

__device__ __forceinline__ void mma_f16(float c[4], const uint32_t a[4], const uint32_t b[2]) {
    asm volatile(
        "mma.sync.aligned.m16n8k16.row.col.f32.f16.f16.f32 "
        "{%0,%1,%2,%3}, {%4,%5,%6,%7}, {%8,%9}, {%0,%1,%2,%3};"
        : "+f"(c[0]), "+f"(c[1]), "+f"(c[2]), "+f"(c[3])
        : "r"(a[0]), "r"(a[1]), "r"(a[2]), "r"(a[3]), "r"(b[0]), "r"(b[1]));
}

__device__ __forceinline__ void cp_async16(uint32_t smem_addr, const void* gptr) {
    asm volatile("cp.async.cg.shared.global [%0], [%1], 16;"
                 :: "r"(smem_addr), "l"(gptr));
}
__device__ __forceinline__ void cp_commit() { asm volatile("cp.async.commit_group;"); }
template<int N>
__device__ __forceinline__ void cp_wait() { asm volatile("cp.async.wait_group %0;" :: "n"(N)); }

// ---------------- weight transpose + fp16 round ----------------
__global__ __launch_bounds__(256) void transpose_h_kernel(
    const float* __restrict__ in, __half* __restrict__ out, int K, int N)
{
    __shared__ float t[32][33];
    const int n0 = blockIdx.x * 32, k0 = blockIdx.y * 32;
    const int tx = threadIdx.x & 31, ty = threadIdx.x >> 5;
    #pragma unroll
    for (int i = 0; i < 32; i += 8)
        t[ty + i][tx] = in[(size_t)(k0 + ty + i) * N + n0 + tx];
    __syncthreads();
    #pragma unroll
    for (int i = 0; i < 32; i += 8)
        out[(size_t)(n0 + ty + i) * K + k0 + tx] = __float2half_rn(t[tx][ty + i]);
}

// ---------------- LayerNorm: warp per row; fp16 output ----------------
__global__ __launch_bounds__(256) void ln_kernel(const float* __restrict__ x,
    const float* __restrict__ g, const float* __restrict__ b, __half* __restrict__ out)
{
    const int row  = blockIdx.x * 8 + (threadIdx.x >> 5);
    const int lane = threadIdx.x & 31;
    const float4* xr = reinterpret_cast<const float4*>(x + (size_t)row * BDIM);
    float4 v[8];
    float s = 0.0f;
    #pragma unroll
    for (int i = 0; i < 8; i++) {
        v[i] = xr[lane + 32 * i];
        s += v[i].x + v[i].y + v[i].z + v[i].w;
    }
    #pragma unroll
    for (int o = 16; o > 0; o >>= 1) s += __shfl_xor_sync(0xffffffffu, s, o);
    const float mu = s * (1.0f / BDIM);
    float q = 0.0f;
    #pragma unroll
    for (int i = 0; i < 8; i++) {
        v[i].x -= mu; v[i].y -= mu; v[i].z -= mu; v[i].w -= mu;
        q += v[i].x*v[i].x + v[i].y*v[i].y + v[i].z*v[i].z + v[i].w*v[i].w;
    }
    #pragma unroll
    for (int o = 16; o > 0; o >>= 1) q += __shfl_xor_sync(0xffffffffu, q, o);
    const float rinv = rsqrtf(q * (1.0f / BDIM) + 1e-5f);
    __half* orow = out + (size_t)row * BDIM;
    #pragma unroll
    for (int i = 0; i < 8; i++) {
        float4 gg = reinterpret_cast<const float4*>(g)[lane + 32 * i];
        float4 bb = reinterpret_cast<const float4*>(b)[lane + 32 * i];
        __half2 h01 = __floats2half2_rn(v[i].x * rinv * gg.x + bb.x,
                                        v[i].y * rinv * gg.y + bb.y);
        __half2 h23 = __floats2half2_rn(v[i].z * rinv * gg.z + bb.z,
                                        v[i].w * rinv * gg.w + bb.w);
        uint2 u = { *reinterpret_cast<uint32_t*>(&h01), *reinterpret_cast<uint32_t*>(&h23) };
        *reinterpret_cast<uint2*>(orow + (lane + 32 * i) * 4) = u;
    }
}

// ---------------- 3-stage cp.async FP16 GEMM: 128 threads, warp 64x64 ----------------
enum { EPI_BIAS = 0, EPI_GELU = 1, EPI_RESGATE = 2 };

#define FSTAGES 3
#define FSTAGE_B 32768
#define GEMM_SMEM (FSTAGES*FSTAGE_B)   // 98304 bytes

template<int EPI>
__global__ __launch_bounds__(128) void h16gemm_kernel(
    const __half* __restrict__ A, const __half* __restrict__ Wt,
    const float* __restrict__ bias, const float* __restrict__ res,
    const float* __restrict__ gate, void* __restrict__ Cv, void* __restrict__ Cv2,
    int M, int N, int K)
{
    constexpr int BK = 64;
    extern __shared__ uint32_t sm[];
    const uint32_t sm_u = (uint32_t)__cvta_generic_to_shared(sm);

    const int tid  = threadIdx.x;
    const int lane = tid & 31;
    const int wid  = tid >> 5;
    const int g    = lane >> 2;
    const int t4   = lane & 3;
    const int mWarp = (wid >> 1) * 64;
    const int nWarp = (wid & 1) * 64;

    const int lrow   = tid >> 3;
    const int lchunk = tid & 7;
    const uint32_t swb = (uint32_t)((lchunk * 16) ^ ((lrow & 3) << 5));

    const __half* Ap = A  + (size_t)(blockIdx.y * 128 + lrow) * K + lchunk * 8;
    const __half* Bp = Wt + (size_t)(blockIdx.x * 128 + lrow) * K + lchunk * 8;

    const int nT = K / BK;

    #pragma unroll
    for (int t = 0; t < FSTAGES - 1; t++) {
        const uint32_t ab = sm_u + t * FSTAGE_B;
        #pragma unroll
        for (int p = 0; p < 8; p++) {
            cp_async16(ab + (uint32_t)((lrow + p * 16) * 128) + swb,
                       Ap + (size_t)t * BK + (size_t)(p * 16) * K);
            cp_async16(ab + 16384u + (uint32_t)((lrow + p * 16) * 128) + swb,
                       Bp + (size_t)t * BK + (size_t)(p * 16) * K);
        }
        cp_commit();
    }

    float acc[4][8][4] = {};

    for (int t = 0; t < nT; t++) {
        cp_wait<FSTAGES - 2>();
        __syncthreads();

        const int tn = t + FSTAGES - 1;
        if (tn < nT) {
            int sl = tn % FSTAGES;
            const uint32_t ab = sm_u + sl * FSTAGE_B;
            #pragma unroll
            for (int p = 0; p < 8; p++) {
                cp_async16(ab + (uint32_t)((lrow + p * 16) * 128) + swb,
                           Ap + (size_t)tn * BK + (size_t)(p * 16) * K);
                cp_async16(ab + 16384u + (uint32_t)((lrow + p * 16) * 128) + swb,
                           Bp + (size_t)tn * BK + (size_t)(p * 16) * K);
            }
        }
        cp_commit();

        const uint32_t aB = sm_u + (t % FSTAGES) * FSTAGE_B;
        const uint32_t bB = aB + 16384u;
        const uint32_t gsw = (uint32_t)((g & 3) << 5);
        #pragma unroll
        for (int kc = 0; kc < 4; kc++) {
            const uint32_t koff = (uint32_t)((kc * 32 + 8 * t4)) ^ gsw;
            uint32_t bf[8][2];
            #pragma unroll
            for (int ni = 0; ni < 8; ni++) {
                uint2 bb;
                asm volatile("ld.shared.v2.b32 {%0,%1}, [%2];"
                             : "=r"(bb.x), "=r"(bb.y)
                             : "r"(bB + (uint32_t)((nWarp + ni * 8 + g) * 128) + koff));
                bf[ni][0] = bb.x; bf[ni][1] = bb.y;
            }
            #pragma unroll
            for (int mi = 0; mi < 4; mi++) {
                const int mb = mWarp + mi * 16;
                uint2 a0, a1;
                asm volatile("ld.shared.v2.b32 {%0,%1}, [%2];"
                             : "=r"(a0.x), "=r"(a0.y)
                             : "r"(aB + (uint32_t)((mb + g) * 128) + koff));
                asm volatile("ld.shared.v2.b32 {%0,%1}, [%2];"
                             : "=r"(a1.x), "=r"(a1.y)
                             : "r"(aB + (uint32_t)((mb + g + 8) * 128) + koff));
                uint32_t af[4] = { a0.x, a1.x, a0.y, a1.y };
                #pragma unroll
                for (int ni = 0; ni < 8; ni++)
                    mma_f16(acc[mi][ni], af, bf[ni]);
            }
        }
    }

    // epilogue
    const float gt = (EPI == EPI_RESGATE) ? gate[0] : 0.0f;
    #pragma unroll
    for (int mi = 0; mi < 4; mi++) {
        const int row0 = blockIdx.y * 128 + mWarp + mi * 16 + g;
        #pragma unroll
        for (int ni = 0; ni < 8; ni++) {
            const int col = blockIdx.x * 128 + nWarp + ni * 8 + t4 * 2;
            const float b0 = bias[col], b1 = bias[col + 1];
            #pragma unroll
            for (int h = 0; h < 2; h++) {
                const int row = row0 + h * 8;
                float v0 = acc[mi][ni][2 * h + 0] + b0;
                float v1 = acc[mi][ni][2 * h + 1] + b1;
                if (EPI == EPI_BIAS) {   // qkv: Q,K (cols<2048) fp16; V (cols>=2048) f32 tf32-rounded
                    if (col < 2 * BDIM) {
                        __half2 hv = __floats2half2_rn(v0, v1);
                        *reinterpret_cast<uint32_t*>((__half*)Cv2 + (size_t)row * (2 * BDIM) + col) =
                            *reinterpret_cast<uint32_t*>(&hv);
                    } else {
                        float* C = (float*)Cv;
                        *reinterpret_cast<float2*>(C + (size_t)row * N + col) =
                            make_float2(f2tff(v0), f2tff(v1));
                    }
                }
                if (EPI == EPI_GELU) {   // fp16 out
                    v0 = 0.5f * v0 * (1.0f + erff(v0 * 0.70710678118654752f));
                    v1 = 0.5f * v1 * (1.0f + erff(v1 * 0.70710678118654752f));
                    __half2 hv = __floats2half2_rn(v0, v1);
                    *reinterpret_cast<uint32_t*>((__half*)Cv + (size_t)row * N + col) =
                        *reinterpret_cast<uint32_t*>(&hv);
                }
                if (EPI == EPI_RESGATE) {
                    float* C = (float*)Cv;
                    const size_t off = (size_t)row * N + col;
                    *reinterpret_cast<float2*>(C + off) =
                        make_float2(res[off] + gt * v0, res[off + 1] + gt * v1);
                }
            }
        }
    }
}

// ---------------- Fused flash attention: fp16 S-phase (Q,K fp16), tf32 PV (V f32) ----------------
#define KSTH 80                      // K smem stride in halves; frag banks 8g+2t4 conflict-free
#define VST  76                      // V smem stride in floats
#define K_BYTES (64*KSTH*2)          // 10240
#define V_BYTES (64*VST*4)           // 19456
#define SLOT_B  (K_BYTES+V_BYTES)    // 29696
#define MK_B    (2*SLOT_B)           // 59392
#define REL_B   (MK_B + 512)         // 59904
#define FL_SMEM (REL_B + 8192)       // 68096 bytes

__global__ __launch_bounds__(256, 2) void flash_attn_kernel(
    const __half* __restrict__ qkvh, const float* __restrict__ qkvf,
    const int* __restrict__ mask, const float* __restrict__ rel,
    __half* __restrict__ ctx)
{
    constexpr float SCALE = 0.125f;
    constexpr float L2E = 1.4426950408889634f;

    extern __shared__ __align__(16) char smc[];
    const uint32_t sm_u = (uint32_t)__cvta_generic_to_shared(smc);
    const int* mki  = reinterpret_cast<const int*>(smc + MK_B);
    float* rel_s    = reinterpret_cast<float*>(smc + REL_B);
    __half* Qst     = reinterpret_cast<__half*>(smc + SLOT_B);   // overlays KV slot 1

    const int bh = blockIdx.y;
    const int b = bh >> 4, h = bh & 15;
    const int i0 = blockIdx.x * 128;
    const int tid = threadIdx.x, lane = tid & 31, w = tid >> 5;
    const int g = lane >> 2, t4 = lane & 3;

    // K loader mapping: row ldr (0..63), 32B chunk kc (0..3)
    const int ldr = tid >> 2;
    const int kc  = tid & 3;
    const __half* khbase = qkvh + (size_t)(b * NSEQ + ldr) * (2 * BDIM) + BDIM + h * HDIM + kc * 16;
    // V loader: row ldr, 64B chunk kc
    const float* vbase = qkvf + (size_t)(b * NSEQ + ldr) * (3 * BDIM) + 2 * BDIM + h * HDIM + kc * 16;

    // prologue: tile 0 -> slot 0
    {
        const uint32_t kdst = sm_u + (uint32_t)(ldr * (KSTH * 2) + kc * 32);
        cp_async16(kdst, khbase);
        cp_async16(kdst + 16, khbase + 8);
        const uint32_t vdst = sm_u + (uint32_t)(K_BYTES + (ldr * VST + kc * 16) * 4);
        #pragma unroll
        for (int i = 0; i < 4; i++)
            cp_async16(vdst + 16 * i, vbase + 4 * i);
        if (tid < 16)
            cp_async16(sm_u + (uint32_t)(MK_B + tid * 16), mask + b * NSEQ + tid * 4);
        cp_commit();
    }

    for (int idx = tid; idx < 2 * MAXSEQ - 1; idx += 256)
        rel_s[idx] = rel[(size_t)idx * NHEADS + h];

    // stage Q tile 128x64 fp16 into slot-1 region
    {
        const int r = tid >> 1;
        const int c0 = (tid & 1) * 32;   // halves
        const __half* qp = qkvh + (size_t)(b * NSEQ + i0 + r) * (2 * BDIM) + h * HDIM + c0;
        #pragma unroll
        for (int i = 0; i < 4; i++)
            *reinterpret_cast<uint4*>(Qst + r * KSTH + c0 + 8 * i) =
                *reinterpret_cast<const uint4*>(qp + 8 * i);
    }
    __syncthreads();

    // Q a-fragments fp16 (k-slot bijection: lane t4 -> k {4t4..4t4+3})
    uint32_t Qa[4][4];
    #pragma unroll
    for (int kt = 0; kt < 4; kt++) {
        uint2 q0 = *reinterpret_cast<const uint2*>(Qst + (w * 16 + g) * KSTH + kt * 16 + 4 * t4);
        uint2 q1 = *reinterpret_cast<const uint2*>(Qst + (w * 16 + g + 8) * KSTH + kt * 16 + 4 * t4);
        Qa[kt][0] = q0.x; Qa[kt][1] = q1.x; Qa[kt][2] = q0.y; Qa[kt][3] = q1.y;
    }

    const int irow0 = i0 + w * 16 + g;
    const int irow1 = irow0 + 8;
    const int mi0 = mask[b * NSEQ + irow0];
    const int mi1 = mask[b * NSEQ + irow1];

    float m0 = -INFINITY, m1 = -INFINITY, l0 = 0.0f, l1 = 0.0f;
    float OcT[4][2][4] = {};

    for (int jt = 0; jt < NSEQ / 64; jt++) {
        cp_wait<0>();
        __syncthreads();

        if (jt + 1 < NSEQ / 64) {
            const int ns = (jt + 1) & 1;
            const __half* kp = khbase + (size_t)(jt + 1) * 64 * (2 * BDIM);
            const float* vp = vbase + (size_t)(jt + 1) * 64 * (3 * BDIM);
            const uint32_t kdst = sm_u + (uint32_t)(ns * SLOT_B + ldr * (KSTH * 2) + kc * 32);
            cp_async16(kdst, kp);
            cp_async16(kdst + 16, kp + 8);
            const uint32_t vdst = sm_u + (uint32_t)(ns * SLOT_B + K_BYTES + (ldr * VST + kc * 16) * 4);
            #pragma unroll
            for (int i = 0; i < 4; i++)
                cp_async16(vdst + 16 * i, vp + 4 * i);
            if (tid < 16)
                cp_async16(sm_u + (uint32_t)(MK_B + ns * 256 + tid * 16),
                           mask + b * NSEQ + (jt + 1) * 64 + tid * 4);
            cp_commit();
        }

        const int slot = jt & 1;
        const __half* Ks = reinterpret_cast<const __half*>(smc + slot * SLOT_B);
        const uint32_t* Vs = reinterpret_cast<const uint32_t*>(smc + slot * SLOT_B + K_BYTES);
        const int* mkp = mki + slot * 64;

        // S = Q @ K^T  (fp16 mma, k16)
        float S[8][4] = {};
        #pragma unroll
        for (int nt = 0; nt < 8; nt++) {
            #pragma unroll
            for (int kt = 0; kt < 4; kt++) {
                uint2 kk = *reinterpret_cast<const uint2*>(Ks + (nt * 8 + g) * KSTH + kt * 16 + 4 * t4);
                uint32_t bf[2] = { kk.x, kk.y };
                mma_f16(S[nt], Qa[kt], bf);
            }
        }

        float tmax0 = -INFINITY, tmax1 = -INFINITY;
        #pragma unroll
        for (int nt = 0; nt < 8; nt++) {
            const int j0 = jt * 64 + nt * 8 + 2 * t4;
            const int mk0 = mkp[nt * 8 + 2 * t4];
            const int mk1 = mkp[nt * 8 + 2 * t4 + 1];
            float s0 = S[nt][0] * SCALE + rel_s[irow0 - j0 + (MAXSEQ - 1)];
            float s1 = S[nt][1] * SCALE + rel_s[irow0 - j0 - 1 + (MAXSEQ - 1)];
            float s2 = S[nt][2] * SCALE + rel_s[irow1 - j0 + (MAXSEQ - 1)];
            float s3 = S[nt][3] * SCALE + rel_s[irow1 - j0 - 1 + (MAXSEQ - 1)];
            if (mi0 == 0 || mk0 == 0) s0 = -1e9f;
            if (mi0 == 0 || mk1 == 0) s1 = -1e9f;
            if (mi1 == 0 || mk0 == 0) s2 = -1e9f;
            if (mi1 == 0 || mk1 == 0) s3 = -1e9f;
            S[nt][0] = s0; S[nt][1] = s1; S[nt][2] = s2; S[nt][3] = s3;
            tmax0 = fmaxf(tmax0, fmaxf(s0, s1));
            tmax1 = fmaxf(tmax1, fmaxf(s2, s3));
        }
        tmax0 = fmaxf(tmax0, __shfl_xor_sync(0xffffffffu, tmax0, 1));
        tmax0 = fmaxf(tmax0, __shfl_xor_sync(0xffffffffu, tmax0, 2));
        tmax1 = fmaxf(tmax1, __shfl_xor_sync(0xffffffffu, tmax1, 1));
        tmax1 = fmaxf(tmax1, __shfl_xor_sync(0xffffffffu, tmax1, 2));

        const float mn0 = fmaxf(m0, tmax0);
        const float mn1 = fmaxf(m1, tmax1);
        const float sc0 = exp2f((m0 - mn0) * L2E);
        const float sc1 = exp2f((m1 - mn1) * L2E);
        m0 = mn0; m1 = mn1;

        float ts0 = 0.0f, ts1 = 0.0f;
        #pragma unroll
        for (int nt = 0; nt < 8; nt++) {
            S[nt][0] = exp2f((S[nt][0] - mn0) * L2E);
            S[nt][1] = exp2f((S[nt][1] - mn0) * L2E);
            S[nt][2] = exp2f((S[nt][2] - mn1) * L2E);
            S[nt][3] = exp2f((S[nt][3] - mn1) * L2E);
            ts0 += S[nt][0] + S[nt][1];
            ts1 += S[nt][2] + S[nt][3];
        }
        ts0 += __shfl_xor_sync(0xffffffffu, ts0, 1);
        ts0 += __shfl_xor_sync(0xffffffffu, ts0, 2);
        ts1 += __shfl_xor_sync(0xffffffffu, ts1, 1);
        ts1 += __shfl_xor_sync(0xffffffffu, ts1, 2);
        l0 = l0 * sc0 + ts0;
        l1 = l1 * sc1 + ts1;

        const float scA = __shfl_sync(0xffffffffu, sc0, 8 * t4);
        const float scB = __shfl_sync(0xffffffffu, sc0, 8 * t4 + 4);
        const float scC = __shfl_sync(0xffffffffu, sc1, 8 * t4);
        const float scD = __shfl_sync(0xffffffffu, sc1, 8 * t4 + 4);
        #pragma unroll
        for (int mi = 0; mi < 4; mi++) {
            OcT[mi][0][0] *= scA; OcT[mi][0][1] *= scB;
            OcT[mi][0][2] *= scA; OcT[mi][0][3] *= scB;
            OcT[mi][1][0] *= scC; OcT[mi][1][1] *= scD;
            OcT[mi][1][2] *= scC; OcT[mi][1][3] *= scD;
        }

        // O^T += V^T @ P^T (tf32; b-frag = S regs via k-slot bijection)
        #pragma unroll
        for (int kt = 0; kt < 8; kt++) {
            uint32_t b0t[2] = { f2tf(S[kt][0]), f2tf(S[kt][1]) };
            uint32_t b1t[2] = { f2tf(S[kt][2]), f2tf(S[kt][3]) };
            const uint32_t* vr0 = &Vs[(kt * 8 + 2 * t4) * VST];
            const uint32_t* vr1 = vr0 + VST;
            #pragma unroll
            for (int mi = 0; mi < 4; mi++) {
                const int d0 = mi * 16 + g;
                uint32_t a[4];
                a[0] = vr0[d0];
                a[1] = vr0[d0 + 8];
                a[2] = vr1[d0];
                a[3] = vr1[d0 + 8];
                mma_tf32(OcT[mi][0], a, b0t);
                mma_tf32(OcT[mi][1], a, b1t);
            }
        }
    }

    // writeback ctx = O / l -> fp16
    const float inv0 = 1.0f / l0;
    const float inv1 = 1.0f / l1;
    const float iA = __shfl_sync(0xffffffffu, inv0, 8 * t4);
    const float iB = __shfl_sync(0xffffffffu, inv0, 8 * t4 + 4);
    const float iC = __shfl_sync(0xffffffffu, inv1, 8 * t4);
    const float iD = __shfl_sync(0xffffffffu, inv1, 8 * t4 + 4);
    #pragma unroll
    for (int mi = 0; mi < 4; mi++) {
        const int col = h * HDIM + mi * 16 + g;
        #pragma unroll
        for (int ni = 0; ni < 2; ni++) {
            const int r0 = i0 + w * 16 + ni * 8 + 2 * t4;
            const float f0 = ni ? iC : iA;
            const float f1 = ni ? iD : iB;
            __half* c0 = ctx + (size_t)(b * NSEQ + r0) * BDIM + col;
            __half* c1 = ctx + (size_t)(b * NSEQ + r0 + 1) * BDIM + col;
            c0[0] = __float2half_rn(OcT[mi][ni][0] * f0);
            c1[0] = __float2half_rn(OcT[mi][ni][1] * f1);
            c0[8] = __float2half_rn(OcT[mi][ni][2] * f0);
            c1[8] = __float2half_rn(OcT[mi][ni][3] * f1);
        }
    }
}

// ---------------- launch ----------------
extern "C" void kernel_launch(void* const* d_in, const int* in_sizes, int n_in,
                              void* d_out, int out_size)
{
    const float* x      = (const float*)d_in[0];
    const int*   mask   = (const int*)  d_in[1];
    const float* ln1_g  = (const float*)d_in[2];
    const float* ln1_b  = (const float*)d_in[3];
    const float* qkv_w  = (const float*)d_in[4];
    const float* qkv_b  = (const float*)d_in[5];
    const float* proj_w = (const float*)d_in[6];
    const float* proj_b = (const float*)d_in[7];
    const float* rel    = (const float*)d_in[8];
    const float* ln2_g  = (const float*)d_in[9];
    const float* ln2_b  = (const float*)d_in[10];
    const float* w1     = (const float*)d_in[11];
    const float* b1     = (const float*)d_in[12];
    const float* w2     = (const float*)d_in[13];
    const float* b2     = (const float*)d_in[14];
    const float* gate1  = (const float*)d_in[15];
    const float* gate2  = (const float*)d_in[16];
    float* out = (float*)d_out;

    __half *xn, *ctx, *mlp, *qkvw, *projw, *w1t, *w2t, *qkvh;
    float *qkv, *y;
    cudaGetSymbolAddress((void**)&xn,    g_xn);
    cudaGetSymbolAddress((void**)&qkv,   g_qkv);
    cudaGetSymbolAddress((void**)&qkvh,  g_qkvh);
    cudaGetSymbolAddress((void**)&ctx,   g_ctx);
    cudaGetSymbolAddress((void**)&y,     g_y);
    cudaGetSymbolAddress((void**)&mlp,   g_mlp);
    cudaGetSymbolAddress((void**)&qkvw,  g_qkvw);
    cudaGetSymbolAddress((void**)&projw, g_projw);
    cudaGetSymbolAddress((void**)&w1t,   g_w1);
    cudaGetSymbolAddress((void**)&w2t,   g_w2);

    static bool attr_set = false;
    if (!attr_set) {
        cudaFuncSetAttribute(h16gemm_kernel<EPI_BIAS>,
                             cudaFuncAttributeMaxDynamicSharedMemorySize, GEMM_SMEM);
        cudaFuncSetAttribute(h16gemm_kernel<EPI_GELU>,
                             cudaFuncAttributeMaxDynamicSharedMemorySize, GEMM_SMEM);
        cudaFuncSetAttribute(h16gemm_kernel<EPI_RESGATE>,
                             cudaFuncAttributeMaxDynamicSharedMemorySize, GEMM_SMEM);
        cudaFuncSetAttribute(flash_attn_kernel,
                             cudaFuncAttributeMaxDynamicSharedMemorySize, FL_SMEM);
        attr_set = true;
    }

    // 0) transpose + fp16-round weights -> [N, K] K-major
    transpose_h_kernel<<<dim3(3*BDIM/32, BDIM/32), 256>>>(qkv_w, qkvw, BDIM, 3*BDIM);
    transpose_h_kernel<<<dim3(BDIM/32,   BDIM/32), 256>>>(proj_w, projw, BDIM, BDIM);
    transpose_h_kernel<<<dim3(4*BDIM/32, BDIM/32), 256>>>(w1, w1t, BDIM, 4*BDIM);
    transpose_h_kernel<<<dim3(BDIM/32, 4*BDIM/32), 256>>>(w2, w2t, 4*BDIM, BDIM);

    // 1) LN1 -> fp16
    ln_kernel<<<ROWS / 8, 256>>>(x, ln1_g, ln1_b, xn);
    // 2) qkv: Q,K -> fp16 buf; V -> f32 buf (tf32-rounded)
    h16gemm_kernel<EPI_BIAS><<<dim3(3 * BDIM / 128, ROWS / 128), 128, GEMM_SMEM>>>(
        xn, qkvw, qkv_b, nullptr, nullptr, qkv, qkvh, ROWS, 3 * BDIM, BDIM);
    // 3) fused attention -> ctx (fp16)
    flash_attn_kernel<<<dim3(NSEQ / 128, NB * NHEADS), 256, FL_SMEM>>>(qkvh, qkv, mask, rel, ctx);
    // 4) y = x + gate1 * (ctx @ proj_w + proj_b)
    h16gemm_kernel<EPI_RESGATE><<<dim3(BDIM / 128, ROWS / 128), 128, GEMM_SMEM>>>(
        ctx, projw, proj_b, x, gate1, y, nullptr, ROWS, BDIM, BDIM);
    // 5) LN2 -> fp16
    ln_kernel<<<ROWS / 8, 256>>>(y, ln2_g, ln2_b, xn);
    // 6) mlp = gelu(xn @ w1 + b1) -> fp16
    h16gemm_kernel<EPI_GELU><<<dim3(4 * BDIM / 128, ROWS / 128), 128, GEMM_SMEM>>>(
        xn, w1t, b1, nullptr, nullptr, mlp, nullptr, ROWS, 4 * BDIM, BDIM);
    // 7) out = y + gate2 * (mlp @ w2 + b2)
    h16gemm_kernel<EPI_RESGATE><<<dim3(BDIM / 128, ROWS / 128), 128, GEMM_SMEM>>>(
        mlp, w2t, b2, y, gate2, out, nullptr, ROWS, BDIM, 4 * BDIM);
}

// round 14
// speedup vs baseline: 1.9564x; 1.0903x over previous
#include <cuda_runtime.h>
#include <cuda_fp16.h>
#include <math.h>
#include <stdint.h>

#define BDIM 1024
#define NB 4
#define NSEQ 1024
#define NHEADS 16
#define HDIM 64
#define ROWS (NB*NSEQ)   // 4096
#define MAXSEQ 1024

// ---------------- scratch (device globals; no allocation allowed) ----------------
__device__ __half g_xn[(size_t)ROWS*BDIM];              // fp16 LN out
__device__ float  g_qkv[(size_t)ROWS*3*BDIM];           // V third used (f32 raw)
__device__ __half g_qkvh[(size_t)ROWS*2*BDIM];          // Q,K fp16
__device__ __half g_vt[(size_t)ROWS*BDIM];              // V^T fp16: [bh*64+d][j]
__device__ __half g_ctx[(size_t)ROWS*BDIM];             // fp16
__device__ float  g_y[(size_t)ROWS*BDIM];
__device__ __half g_mlp[(size_t)ROWS*4*BDIM];
// fp16 TRANSPOSED weights [N, K] K-major
__device__ __half g_qkvw[(size_t)BDIM*3*BDIM];
__device__ __half g_projw[(size_t)BDIM*BDIM];
__device__ __half g_w1[(size_t)BDIM*4*BDIM];
__device__ __half g_w2[(size_t)4*BDIM*BDIM];

// ---------------- helpers ----------------
__device__ __forceinline__ void mma_f16(float c[4], const uint32_t a[4], const uint32_t b[2]) {
    asm volatile(
        "mma.sync.aligned.m16n8k16.row.col.f32.f16.f16.f32 "
        "{%0,%1,%2,%3}, {%4,%5,%6,%7}, {%8,%9}, {%0,%1,%2,%3};"
        : "+f"(c[0]), "+f"(c[1]), "+f"(c[2]), "+f"(c[3])
        : "r"(a[0]), "r"(a[1]), "r"(a[2]), "r"(a[3]), "r"(b[0]), "r"(b[1]));
}

__device__ __forceinline__ void cp_async16(uint32_t smem_addr, const void* gptr) {
    asm volatile("cp.async.cg.shared.global [%0], [%1], 16;"
                 :: "r"(smem_addr), "l"(gptr));
}
__device__ __forceinline__ void cp_commit() { asm volatile("cp.async.commit_group;"); }
template<int N>
__device__ __forceinline__ void cp_wait() { asm volatile("cp.async.wait_group %0;" :: "n"(N)); }

__device__ __forceinline__ uint32_t h2u(__half2 h) { return *reinterpret_cast<uint32_t*>(&h); }

// ---------------- merged weight transpose + fp16 round (single launch) ----------------
__global__ __launch_bounds__(256) void transpose_all_kernel(
    const float* __restrict__ qkv_w, __half* __restrict__ qkvw,
    const float* __restrict__ proj_w, __half* __restrict__ projw,
    const float* __restrict__ w1, __half* __restrict__ w1t,
    const float* __restrict__ w2, __half* __restrict__ w2t)
{
    __shared__ float t[32][33];
    const int bid = blockIdx.x;
    const float* in; __half* out; int K, N, bx, by;
    if (bid < 3072)      { in = qkv_w;  out = qkvw;  K = 1024; N = 3072; bx = bid % 96;  by = bid / 96; }
    else if (bid < 4096) { int q = bid - 3072; in = proj_w; out = projw; K = 1024; N = 1024; bx = q % 32;  by = q / 32; }
    else if (bid < 8192) { int q = bid - 4096; in = w1;     out = w1t;   K = 1024; N = 4096; bx = q % 128; by = q / 128; }
    else                 { int q = bid - 8192; in = w2;     out = w2t;   K = 4096; N = 1024; bx = q % 32;  by = q / 32; }
    const int n0 = bx * 32, k0 = by * 32;
    const int tx = threadIdx.x & 31, ty = threadIdx.x >> 5;
    #pragma unroll
    for (int i = 0; i < 32; i += 8)
        t[ty + i][tx] = in[(size_t)(k0 + ty + i) * N + n0 + tx];
    __syncthreads();
    #pragma unroll
    for (int i = 0; i < 32; i += 8)
        out[(size_t)(n0 + ty + i) * K + k0 + tx] = __float2half_rn(t[tx][ty + i]);
}

// ---------------- V transpose: g_qkv f32 [token][2048+h*64+d] -> g_vt fp16 [bh*64+d][j] ----------------
__global__ __launch_bounds__(256) void transpose_v_kernel(
    const float* __restrict__ qkvf, __half* __restrict__ vt)
{
    __shared__ float t[32][33];
    const int bh = blockIdx.z;
    const int b = bh >> 4, h = bh & 15;
    const int j0 = blockIdx.x * 32, d0 = blockIdx.y * 32;
    const int tx = threadIdx.x & 31, ty = threadIdx.x >> 5;
    #pragma unroll
    for (int i = 0; i < 32; i += 8)
        t[ty + i][tx] = qkvf[(size_t)(b * NSEQ + j0 + ty + i) * (3 * BDIM) + 2 * BDIM + h * HDIM + d0 + tx];
    __syncthreads();
    #pragma unroll
    for (int i = 0; i < 32; i += 8)
        vt[(size_t)(bh * HDIM + d0 + ty + i) * NSEQ + j0 + tx] = __float2half_rn(t[tx][ty + i]);
}

// ---------------- LayerNorm: warp per row; fp16 output ----------------
__global__ __launch_bounds__(256) void ln_kernel(const float* __restrict__ x,
    const float* __restrict__ g, const float* __restrict__ b, __half* __restrict__ out)
{
    const int row  = blockIdx.x * 8 + (threadIdx.x >> 5);
    const int lane = threadIdx.x & 31;
    const float4* xr = reinterpret_cast<const float4*>(x + (size_t)row * BDIM);
    float4 v[8];
    float s = 0.0f;
    #pragma unroll
    for (int i = 0; i < 8; i++) {
        v[i] = xr[lane + 32 * i];
        s += v[i].x + v[i].y + v[i].z + v[i].w;
    }
    #pragma unroll
    for (int o = 16; o > 0; o >>= 1) s += __shfl_xor_sync(0xffffffffu, s, o);
    const float mu = s * (1.0f / BDIM);
    float q = 0.0f;
    #pragma unroll
    for (int i = 0; i < 8; i++) {
        v[i].x -= mu; v[i].y -= mu; v[i].z -= mu; v[i].w -= mu;
        q += v[i].x*v[i].x + v[i].y*v[i].y + v[i].z*v[i].z + v[i].w*v[i].w;
    }
    #pragma unroll
    for (int o = 16; o > 0; o >>= 1) q += __shfl_xor_sync(0xffffffffu, q, o);
    const float rinv = rsqrtf(q * (1.0f / BDIM) + 1e-5f);
    __half* orow = out + (size_t)row * BDIM;
    #pragma unroll
    for (int i = 0; i < 8; i++) {
        float4 gg = reinterpret_cast<const float4*>(g)[lane + 32 * i];
        float4 bb = reinterpret_cast<const float4*>(b)[lane + 32 * i];
        __half2 h01 = __floats2half2_rn(v[i].x * rinv * gg.x + bb.x,
                                        v[i].y * rinv * gg.y + bb.y);
        __half2 h23 = __floats2half2_rn(v[i].z * rinv * gg.z + bb.z,
                                        v[i].w * rinv * gg.w + bb.w);
        uint2 u = { h2u(h01), h2u(h23) };
        *reinterpret_cast<uint2*>(orow + (lane + 32 * i) * 4) = u;
    }
}

// ---------------- 3-stage cp.async FP16 GEMM: 128 threads, warp 64x64 ----------------
enum { EPI_BIAS = 0, EPI_GELU = 1, EPI_RESGATE = 2 };

#define FSTAGES 3
#define FSTAGE_B 32768
#define GEMM_SMEM (FSTAGES*FSTAGE_B)   // 98304 bytes

template<int EPI>
__global__ __launch_bounds__(128) void h16gemm_kernel(
    const __half* __restrict__ A, const __half* __restrict__ Wt,
    const float* __restrict__ bias, const float* __restrict__ res,
    const float* __restrict__ gate, void* __restrict__ Cv, void* __restrict__ Cv2,
    int M, int N, int K)
{
    constexpr int BK = 64;
    extern __shared__ uint32_t sm[];
    const uint32_t sm_u = (uint32_t)__cvta_generic_to_shared(sm);

    const int tid  = threadIdx.x;
    const int lane = tid & 31;
    const int wid  = tid >> 5;
    const int g    = lane >> 2;
    const int t4   = lane & 3;
    const int mWarp = (wid >> 1) * 64;
    const int nWarp = (wid & 1) * 64;

    const int lrow   = tid >> 3;
    const int lchunk = tid & 7;
    const uint32_t swb = (uint32_t)((lchunk * 16) ^ ((lrow & 3) << 5));

    const __half* Ap = A  + (size_t)(blockIdx.y * 128 + lrow) * K + lchunk * 8;
    const __half* Bp = Wt + (size_t)(blockIdx.x * 128 + lrow) * K + lchunk * 8;

    const int nT = K / BK;

    #pragma unroll
    for (int t = 0; t < FSTAGES - 1; t++) {
        const uint32_t ab = sm_u + t * FSTAGE_B;
        #pragma unroll
        for (int p = 0; p < 8; p++) {
            cp_async16(ab + (uint32_t)((lrow + p * 16) * 128) + swb,
                       Ap + (size_t)t * BK + (size_t)(p * 16) * K);
            cp_async16(ab + 16384u + (uint32_t)((lrow + p * 16) * 128) + swb,
                       Bp + (size_t)t * BK + (size_t)(p * 16) * K);
        }
        cp_commit();
    }

    float acc[4][8][4] = {};

    for (int t = 0; t < nT; t++) {
        cp_wait<FSTAGES - 2>();
        __syncthreads();

        const int tn = t + FSTAGES - 1;
        if (tn < nT) {
            int sl = tn % FSTAGES;
            const uint32_t ab = sm_u + sl * FSTAGE_B;
            #pragma unroll
            for (int p = 0; p < 8; p++) {
                cp_async16(ab + (uint32_t)((lrow + p * 16) * 128) + swb,
                           Ap + (size_t)tn * BK + (size_t)(p * 16) * K);
                cp_async16(ab + 16384u + (uint32_t)((lrow + p * 16) * 128) + swb,
                           Bp + (size_t)tn * BK + (size_t)(p * 16) * K);
            }
        }
        cp_commit();

        const uint32_t aB = sm_u + (t % FSTAGES) * FSTAGE_B;
        const uint32_t bB = aB + 16384u;
        const uint32_t gsw = (uint32_t)((g & 3) << 5);
        #pragma unroll
        for (int kc = 0; kc < 4; kc++) {
            const uint32_t koff = (uint32_t)((kc * 32 + 8 * t4)) ^ gsw;
            uint32_t bf[8][2];
            #pragma unroll
            for (int ni = 0; ni < 8; ni++) {
                uint2 bb;
                asm volatile("ld.shared.v2.b32 {%0,%1}, [%2];"
                             : "=r"(bb.x), "=r"(bb.y)
                             : "r"(bB + (uint32_t)((nWarp + ni * 8 + g) * 128) + koff));
                bf[ni][0] = bb.x; bf[ni][1] = bb.y;
            }
            #pragma unroll
            for (int mi = 0; mi < 4; mi++) {
                const int mb = mWarp + mi * 16;
                uint2 a0, a1;
                asm volatile("ld.shared.v2.b32 {%0,%1}, [%2];"
                             : "=r"(a0.x), "=r"(a0.y)
                             : "r"(aB + (uint32_t)((mb + g) * 128) + koff));
                asm volatile("ld.shared.v2.b32 {%0,%1}, [%2];"
                             : "=r"(a1.x), "=r"(a1.y)
                             : "r"(aB + (uint32_t)((mb + g + 8) * 128) + koff));
                uint32_t af[4] = { a0.x, a1.x, a0.y, a1.y };
                #pragma unroll
                for (int ni = 0; ni < 8; ni++)
                    mma_f16(acc[mi][ni], af, bf[ni]);
            }
        }
    }

    // epilogue
    const float gt = (EPI == EPI_RESGATE) ? gate[0] : 0.0f;
    #pragma unroll
    for (int mi = 0; mi < 4; mi++) {
        const int row0 = blockIdx.y * 128 + mWarp + mi * 16 + g;
        #pragma unroll
        for (int ni = 0; ni < 8; ni++) {
            const int col = blockIdx.x * 128 + nWarp + ni * 8 + t4 * 2;
            const float b0 = bias[col], b1 = bias[col + 1];
            #pragma unroll
            for (int h = 0; h < 2; h++) {
                const int row = row0 + h * 8;
                float v0 = acc[mi][ni][2 * h + 0] + b0;
                float v1 = acc[mi][ni][2 * h + 1] + b1;
                if (EPI == EPI_BIAS) {   // Q,K fp16; V raw f32 (transposed->fp16 later)
                    if (col < 2 * BDIM) {
                        *reinterpret_cast<uint32_t*>((__half*)Cv2 + (size_t)row * (2 * BDIM) + col) =
                            h2u(__floats2half2_rn(v0, v1));
                    } else {
                        float* C = (float*)Cv;
                        *reinterpret_cast<float2*>(C + (size_t)row * N + col) = make_float2(v0, v1);
                    }
                }
                if (EPI == EPI_GELU) {
                    v0 = 0.5f * v0 * (1.0f + erff(v0 * 0.70710678118654752f));
                    v1 = 0.5f * v1 * (1.0f + erff(v1 * 0.70710678118654752f));
                    *reinterpret_cast<uint32_t*>((__half*)Cv + (size_t)row * N + col) =
                        h2u(__floats2half2_rn(v0, v1));
                }
                if (EPI == EPI_RESGATE) {
                    float* C = (float*)Cv;
                    const size_t off = (size_t)row * N + col;
                    *reinterpret_cast<float2*>(C + off) =
                        make_float2(res[off] + gt * v0, res[off + 1] + gt * v1);
                }
            }
        }
    }
}

// ---------------- Fused flash attention: full fp16 tensor path ----------------
#define KSTH 80                        // K stride (halves): frag LDS.64 banks 8g+2t4 CF
#define VTH  72                        // V^T stride (halves): frag LDS.32 banks 4g+t4 CF
#define K_BYTES (64*KSTH*2)            // 10240
#define VT_BYTES (64*VTH*2)            // 9216
#define SLOT_B  (K_BYTES+VT_BYTES)     // 19456
#define MK_B    (2*SLOT_B)             // 38912
#define REL_B   (MK_B + 512)           // 39424
#define FL_SMEM (REL_B + 8192)         // 47616 bytes

__global__ __launch_bounds__(256, 2) void flash_attn_kernel(
    const __half* __restrict__ qkvh, const __half* __restrict__ vt,
    const int* __restrict__ mask, const float* __restrict__ rel,
    __half* __restrict__ ctx)
{
    constexpr float SCALE = 0.125f;
    constexpr float L2E = 1.4426950408889634f;

    extern __shared__ __align__(16) char smc[];
    const uint32_t sm_u = (uint32_t)__cvta_generic_to_shared(smc);
    const int* mki  = reinterpret_cast<const int*>(smc + MK_B);
    float* rel_s    = reinterpret_cast<float*>(smc + REL_B);

    const int bh = blockIdx.y;
    const int b = bh >> 4, h = bh & 15;
    const int i0 = blockIdx.x * 128;
    const int tid = threadIdx.x, lane = tid & 31, w = tid >> 5;
    const int g = lane >> 2, t4 = lane & 3;

    // loaders: K rows (tokens) / Vt rows (d)
    const int ldr = tid >> 2;
    const int kc  = tid & 3;
    const __half* khbase = qkvh + (size_t)(b * NSEQ + ldr) * (2 * BDIM) + BDIM + h * HDIM + kc * 16;
    const __half* vtbase = vt + (size_t)(bh * HDIM + ldr) * NSEQ + kc * 16;

    // prologue: tile 0 -> slot 0
    {
        const uint32_t kdst = sm_u + (uint32_t)(ldr * (KSTH * 2) + kc * 32);
        cp_async16(kdst, khbase);
        cp_async16(kdst + 16, khbase + 8);
        const uint32_t vdst = sm_u + (uint32_t)(K_BYTES + ldr * (VTH * 2) + kc * 32);
        cp_async16(vdst, vtbase);
        cp_async16(vdst + 16, vtbase + 8);
        if (tid < 16)
            cp_async16(sm_u + (uint32_t)(MK_B + tid * 16), mask + b * NSEQ + tid * 4);
        cp_commit();
    }

    for (int idx = tid; idx < 2 * MAXSEQ - 1; idx += 256)
        rel_s[idx] = rel[(size_t)idx * NHEADS + h];

    const int irow0 = i0 + w * 16 + g;
    const int irow1 = irow0 + 8;

    // Q a-fragments straight from gmem (k-slot bijection t4 -> k {4t4..4t4+3})
    uint32_t Qa[4][4];
    {
        const __half* q0p = qkvh + (size_t)(b * NSEQ + irow0) * (2 * BDIM) + h * HDIM + 4 * t4;
        const __half* q1p = qkvh + (size_t)(b * NSEQ + irow1) * (2 * BDIM) + h * HDIM + 4 * t4;
        #pragma unroll
        for (int kt = 0; kt < 4; kt++) {
            uint2 a = *reinterpret_cast<const uint2*>(q0p + kt * 16);
            uint2 c = *reinterpret_cast<const uint2*>(q1p + kt * 16);
            Qa[kt][0] = a.x; Qa[kt][1] = c.x; Qa[kt][2] = a.y; Qa[kt][3] = c.y;
        }
    }

    const int mi0 = mask[b * NSEQ + irow0];
    const int mi1 = mask[b * NSEQ + irow1];

    float m0 = -INFINITY, m1 = -INFINITY, l0 = 0.0f, l1 = 0.0f;
    float Oc[8][4] = {};

    for (int jt = 0; jt < NSEQ / 64; jt++) {
        cp_wait<0>();
        __syncthreads();

        if (jt + 1 < NSEQ / 64) {
            const int ns = (jt + 1) & 1;
            const __half* kp = khbase + (size_t)(jt + 1) * 64 * (2 * BDIM);
            const __half* vp = vtbase + (size_t)(jt + 1) * 64;
            const uint32_t kdst = sm_u + (uint32_t)(ns * SLOT_B + ldr * (KSTH * 2) + kc * 32);
            cp_async16(kdst, kp);
            cp_async16(kdst + 16, kp + 8);
            const uint32_t vdst = sm_u + (uint32_t)(ns * SLOT_B + K_BYTES + ldr * (VTH * 2) + kc * 32);
            cp_async16(vdst, vp);
            cp_async16(vdst + 16, vp + 8);
            if (tid < 16)
                cp_async16(sm_u + (uint32_t)(MK_B + ns * 256 + tid * 16),
                           mask + b * NSEQ + (jt + 1) * 64 + tid * 4);
            cp_commit();
        }

        const int slot = jt & 1;
        const __half* Ks = reinterpret_cast<const __half*>(smc + slot * SLOT_B);
        const __half* Vts = reinterpret_cast<const __half*>(smc + slot * SLOT_B + K_BYTES);
        const int* mkp = mki + slot * 64;

        // S = Q @ K^T  (fp16, k16)
        float S[8][4] = {};
        #pragma unroll
        for (int nt = 0; nt < 8; nt++) {
            #pragma unroll
            for (int kt = 0; kt < 4; kt++) {
                uint2 kk = *reinterpret_cast<const uint2*>(Ks + (nt * 8 + g) * KSTH + kt * 16 + 4 * t4);
                uint32_t bf[2] = { kk.x, kk.y };
                mma_f16(S[nt], Qa[kt], bf);
            }
        }

        // scale + rel bias + mask; row max
        float tmax0 = -INFINITY, tmax1 = -INFINITY;
        #pragma unroll
        for (int nt = 0; nt < 8; nt++) {
            const int j0 = jt * 64 + nt * 8 + 2 * t4;
            const int mk0 = mkp[nt * 8 + 2 * t4];
            const int mk1 = mkp[nt * 8 + 2 * t4 + 1];
            float s0 = S[nt][0] * SCALE + rel_s[irow0 - j0 + (MAXSEQ - 1)];
            float s1 = S[nt][1] * SCALE + rel_s[irow0 - j0 - 1 + (MAXSEQ - 1)];
            float s2 = S[nt][2] * SCALE + rel_s[irow1 - j0 + (MAXSEQ - 1)];
            float s3 = S[nt][3] * SCALE + rel_s[irow1 - j0 - 1 + (MAXSEQ - 1)];
            if (mi0 == 0 || mk0 == 0) s0 = -1e9f;
            if (mi0 == 0 || mk1 == 0) s1 = -1e9f;
            if (mi1 == 0 || mk0 == 0) s2 = -1e9f;
            if (mi1 == 0 || mk1 == 0) s3 = -1e9f;
            S[nt][0] = s0; S[nt][1] = s1; S[nt][2] = s2; S[nt][3] = s3;
            tmax0 = fmaxf(tmax0, fmaxf(s0, s1));
            tmax1 = fmaxf(tmax1, fmaxf(s2, s3));
        }
        tmax0 = fmaxf(tmax0, __shfl_xor_sync(0xffffffffu, tmax0, 1));
        tmax0 = fmaxf(tmax0, __shfl_xor_sync(0xffffffffu, tmax0, 2));
        tmax1 = fmaxf(tmax1, __shfl_xor_sync(0xffffffffu, tmax1, 1));
        tmax1 = fmaxf(tmax1, __shfl_xor_sync(0xffffffffu, tmax1, 2));

        const float mn0 = fmaxf(m0, tmax0);
        const float mn1 = fmaxf(m1, tmax1);
        const float sc0 = exp2f((m0 - mn0) * L2E);
        const float sc1 = exp2f((m1 - mn1) * L2E);
        m0 = mn0; m1 = mn1;

        float ts0 = 0.0f, ts1 = 0.0f;
        #pragma unroll
        for (int nt = 0; nt < 8; nt++) {
            S[nt][0] = exp2f((S[nt][0] - mn0) * L2E);
            S[nt][1] = exp2f((S[nt][1] - mn0) * L2E);
            S[nt][2] = exp2f((S[nt][2] - mn1) * L2E);
            S[nt][3] = exp2f((S[nt][3] - mn1) * L2E);
            ts0 += S[nt][0] + S[nt][1];
            ts1 += S[nt][2] + S[nt][3];
        }
        ts0 += __shfl_xor_sync(0xffffffffu, ts0, 1);
        ts0 += __shfl_xor_sync(0xffffffffu, ts0, 2);
        ts1 += __shfl_xor_sync(0xffffffffu, ts1, 1);
        ts1 += __shfl_xor_sync(0xffffffffu, ts1, 2);
        l0 = l0 * sc0 + ts0;
        l1 = l1 * sc1 + ts1;

        // rescale O (per-row: c0,c1 = row g; c2,c3 = row g+8)
        #pragma unroll
        for (int nt = 0; nt < 8; nt++) {
            Oc[nt][0] *= sc0; Oc[nt][1] *= sc0;
            Oc[nt][2] *= sc1; Oc[nt][3] *= sc1;
        }

        // O += P @ V : a-frag = packed S regs (no shuffles), b-frag = V^T smem LDS.32
        #pragma unroll
        for (int kcc = 0; kcc < 4; kcc++) {
            const int nt0 = 2 * kcc, nt1 = nt0 + 1;
            uint32_t af[4];
            af[0] = h2u(__floats2half2_rn(S[nt0][0], S[nt0][1]));
            af[1] = h2u(__floats2half2_rn(S[nt0][2], S[nt0][3]));
            af[2] = h2u(__floats2half2_rn(S[nt1][0], S[nt1][1]));
            af[3] = h2u(__floats2half2_rn(S[nt1][2], S[nt1][3]));
            #pragma unroll
            for (int nt = 0; nt < 8; nt++) {
                const __half* vr = Vts + (nt * 8 + g) * VTH + kcc * 16 + 2 * t4;
                uint32_t bf[2];
                bf[0] = *reinterpret_cast<const uint32_t*>(vr);
                bf[1] = *reinterpret_cast<const uint32_t*>(vr + 8);
                mma_f16(Oc[nt], af, bf);
            }
        }
    }

    // writeback ctx = O / l -> fp16 (coalesced half2, no shuffles)
    const float inv0 = 1.0f / l0;
    const float inv1 = 1.0f / l1;
    #pragma unroll
    for (int nt = 0; nt < 8; nt++) {
        const int col = h * HDIM + nt * 8 + 2 * t4;
        *reinterpret_cast<uint32_t*>(ctx + (size_t)(b * NSEQ + irow0) * BDIM + col) =
            h2u(__floats2half2_rn(Oc[nt][0] * inv0, Oc[nt][1] * inv0));
        *reinterpret_cast<uint32_t*>(ctx + (size_t)(b * NSEQ + irow1) * BDIM + col) =
            h2u(__floats2half2_rn(Oc[nt][2] * inv1, Oc[nt][3] * inv1));
    }
}

// ---------------- launch ----------------
extern "C" void kernel_launch(void* const* d_in, const int* in_sizes, int n_in,
                              void* d_out, int out_size)
{
    const float* x      = (const float*)d_in[0];
    const int*   mask   = (const int*)  d_in[1];
    const float* ln1_g  = (const float*)d_in[2];
    const float* ln1_b  = (const float*)d_in[3];
    const float* qkv_w  = (const float*)d_in[4];
    const float* qkv_b  = (const float*)d_in[5];
    const float* proj_w = (const float*)d_in[6];
    const float* proj_b = (const float*)d_in[7];
    const float* rel    = (const float*)d_in[8];
    const float* ln2_g  = (const float*)d_in[9];
    const float* ln2_b  = (const float*)d_in[10];
    const float* w1     = (const float*)d_in[11];
    const float* b1     = (const float*)d_in[12];
    const float* w2     = (const float*)d_in[13];
    const float* b2     = (const float*)d_in[14];
    const float* gate1  = (const float*)d_in[15];
    const float* gate2  = (const float*)d_in[16];
    float* out = (float*)d_out;

    __half *xn, *ctx, *mlp, *qkvw, *projw, *w1t, *w2t, *qkvh, *vt;
    float *qkv, *y;
    cudaGetSymbolAddress((void**)&xn,    g_xn);
    cudaGetSymbolAddress((void**)&qkv,   g_qkv);
    cudaGetSymbolAddress((void**)&qkvh,  g_qkvh);
    cudaGetSymbolAddress((void**)&vt,    g_vt);
    cudaGetSymbolAddress((void**)&ctx,   g_ctx);
    cudaGetSymbolAddress((void**)&y,     g_y);
    cudaGetSymbolAddress((void**)&mlp,   g_mlp);
    cudaGetSymbolAddress((void**)&qkvw,  g_qkvw);
    cudaGetSymbolAddress((void**)&projw, g_projw);
    cudaGetSymbolAddress((void**)&w1t,   g_w1);
    cudaGetSymbolAddress((void**)&w2t,   g_w2);

    static bool attr_set = false;
    if (!attr_set) {
        cudaFuncSetAttribute(h16gemm_kernel<EPI_BIAS>,
                             cudaFuncAttributeMaxDynamicSharedMemorySize, GEMM_SMEM);
        cudaFuncSetAttribute(h16gemm_kernel<EPI_GELU>,
                             cudaFuncAttributeMaxDynamicSharedMemorySize, GEMM_SMEM);
        cudaFuncSetAttribute(h16gemm_kernel<EPI_RESGATE>,
                             cudaFuncAttributeMaxDynamicSharedMemorySize, GEMM_SMEM);
        cudaFuncSetAttribute(flash_attn_kernel,
                             cudaFuncAttributeMaxDynamicSharedMemorySize, FL_SMEM);
        attr_set = true;
    }

    // 0) all weight transposes (single launch)
    transpose_all_kernel<<<12288, 256>>>(qkv_w, qkvw, proj_w, projw, w1, w1t, w2, w2t);

    // 1) LN1 -> fp16
    ln_kernel<<<ROWS / 8, 256>>>(x, ln1_g, ln1_b, xn);
    // 2) qkv: Q,K -> fp16; V -> f32 raw
    h16gemm_kernel<EPI_BIAS><<<dim3(3 * BDIM / 128, ROWS / 128), 128, GEMM_SMEM>>>(
        xn, qkvw, qkv_b, nullptr, nullptr, qkv, qkvh, ROWS, 3 * BDIM, BDIM);
    // 2b) V -> V^T fp16
    transpose_v_kernel<<<dim3(NSEQ / 32, HDIM / 32, NB * NHEADS), 256>>>(qkv, vt);
    // 3) fused attention -> ctx (fp16)
    flash_attn_kernel<<<dim3(NSEQ / 128, NB * NHEADS), 256, FL_SMEM>>>(qkvh, vt, mask, rel, ctx);
    // 4) y = x + gate1 * (ctx @ proj_w + proj_b)
    h16gemm_kernel<EPI_RESGATE><<<dim3(BDIM / 128, ROWS / 128), 128, GEMM_SMEM>>>(
        ctx, projw, proj_b, x, gate1, y, nullptr, ROWS, BDIM, BDIM);
    // 5) LN2 -> fp16
    ln_kernel<<<ROWS / 8, 256>>>(y, ln2_g, ln2_b, xn);
    // 6) mlp = gelu(xn @ w1 + b1) -> fp16
    h16gemm_kernel<EPI_GELU><<<dim3(4 * BDIM / 128, ROWS / 128), 128, GEMM_SMEM>>>(
        xn, w1t, b1, nullptr, nullptr, mlp, nullptr, ROWS, 4 * BDIM, BDIM);
    // 7) out = y + gate2 * (mlp @ w2 + b2)
    h16gemm_kernel<EPI_RESGATE><<<dim3(BDIM / 128, ROWS / 128), 128, GEMM_SMEM>>>(
        mlp, w2t, b2, y, gate2, out, nullptr, ROWS, BDIM, 4 * BDIM);
}